// round 12
// baseline (speedup 1.0000x reference)
#include <cuda_runtime.h>
#include <cuda_bf16.h>
#include <stdint.h>
#include <math.h>

#define CD 128
#define NMAX 100352
#define EMAX 1700000

// ---------------- device scratch ----------------
__device__ __align__(16) float g_P[(size_t)NMAX * CD];      // fp32 logits OR bf16 conv out
__device__ __align__(16) float g_H[(size_t)NMAX * CD / 2];  // bf16 hidden
__device__ float g_dis[NMAX];
__device__ int   g_cnt[NMAX];
__device__ int   g_off[NMAX];
__device__ int   g_cur[NMAX];
__device__ int   g_bkt[EMAX];
__device__ int   g_part[128];
__device__ __align__(16) __nv_bfloat16 g_Wb[3][CD * CD];    // bf16 W[c_out][c_in]

__device__ __forceinline__ unsigned int pack_bf16x2(float lo, float hi) {
    unsigned int r;
    asm("cvt.rn.bf16x2.f32 %0, %1, %2;" : "=r"(r) : "f"(hi), "f"(lo));
    return r;
}

// ---------------- small structural kernels (champion-exact) ----------------
__global__ void k_zero_cnt(int n) {
    int i = blockIdx.x * blockDim.x + threadIdx.x;
    if (i < n) g_cnt[i] = 0;
}

// vectorized: two edges per thread via int2
__global__ void k_count(const int* __restrict__ col, int E) {
    int E2 = E >> 1;
    const int2* __restrict__ c2 = (const int2*)col;
    for (int e = blockIdx.x * blockDim.x + threadIdx.x; e < E2;
         e += gridDim.x * blockDim.x) {
        int2 c = c2[e];
        atomicAdd(&g_cnt[c.x], 1);
        atomicAdd(&g_cnt[c.y], 1);
    }
    if ((E & 1) && blockIdx.x == 0 && threadIdx.x == 0)
        atomicAdd(&g_cnt[col[E - 1]], 1);
}

__global__ void k_dis(int n) {
    int i = blockIdx.x * blockDim.x + threadIdx.x;
    if (i < n) g_dis[i] = rsqrtf((float)g_cnt[i] + 1.0f);
}

__global__ void k_scan1(int n) {
    __shared__ int wsum[32];
    int tid = threadIdx.x;
    int lane = tid & 31, wid = tid >> 5;
    int i = blockIdx.x * 1024 + tid;
    int x = (i < n) ? g_cnt[i] : 0;
    int v = x;
#pragma unroll
    for (int d = 1; d < 32; d <<= 1) {
        int t = __shfl_up_sync(0xFFFFFFFFu, v, d);
        if (lane >= d) v += t;
    }
    if (lane == 31) wsum[wid] = v;
    __syncthreads();
    if (wid == 0) {
        int w = wsum[lane];
#pragma unroll
        for (int d = 1; d < 32; d <<= 1) {
            int t = __shfl_up_sync(0xFFFFFFFFu, w, d);
            if (lane >= d) w += t;
        }
        wsum[lane] = w;
    }
    __syncthreads();
    int base = (wid > 0) ? wsum[wid - 1] : 0;
    if (i < n) g_off[i] = base + v - x;
    if (tid == 1023) g_part[blockIdx.x] = wsum[31];
}

__global__ void k_scan2(int nb) {
    __shared__ int s[128];
    int tid = threadIdx.x;
    int x = (tid < nb) ? g_part[tid] : 0;
    s[tid] = x;
    __syncthreads();
    for (int d = 1; d < 128; d <<= 1) {
        int t = (tid >= d) ? s[tid - d] : 0;
        __syncthreads();
        s[tid] += t;
        __syncthreads();
    }
    if (tid < nb) g_part[tid] = s[tid] - x;
}

__global__ void k_scan3(int n) {
    int i = blockIdx.x * blockDim.x + threadIdx.x;
    if (i < n) {
        int v = g_off[i] + g_part[i >> 10];
        g_off[i] = v;
        g_cur[i] = v;
    }
}

// vectorized: two edges per thread via int2
__global__ void k_fill(const int* __restrict__ row, const int* __restrict__ col, int E) {
    int E2 = E >> 1;
    const int2* __restrict__ r2 = (const int2*)row;
    const int2* __restrict__ c2 = (const int2*)col;
    for (int e = blockIdx.x * blockDim.x + threadIdx.x; e < E2;
         e += gridDim.x * blockDim.x) {
        int2 c = c2[e];
        int2 r = r2[e];
        int p0 = atomicAdd(&g_cur[c.x], 1);
        g_bkt[p0] = r.x;
        int p1 = atomicAdd(&g_cur[c.y], 1);
        g_bkt[p1] = r.y;
    }
    if ((E & 1) && blockIdx.x == 0 && threadIdx.x == 0) {
        int p = atomicAdd(&g_cur[col[E - 1]], 1);
        g_bkt[p] = row[E - 1];
    }
}

// convert all three weights at once: 3 * 16384 elements
__global__ void k_cvtW3(const float* __restrict__ W1, const float* __restrict__ W2,
                        const float* __restrict__ Wl) {
    int i = blockIdx.x * 256 + threadIdx.x;   // 192 blocks
    int which = i >> 14, j = i & 16383;
    const float* W = (which == 0) ? W1 : (which == 1) ? W2 : Wl;
    g_Wb[which][j] = __float2bfloat16(W[j]);
}

// ---------------- bf16 tensor-core GEMM (champion-exact) ----------------------------
__global__ void __launch_bounds__(256)
k_gemm_bf16(const float* __restrict__ Xf, int useXf, int widx, int outF32, int n) {
    __shared__ __align__(16) __nv_bfloat16 Xs[128][72];
    __shared__ __align__(16) __nv_bfloat16 Ws[128][72];

    const __nv_bfloat16* __restrict__ Hb = (const __nv_bfloat16*)g_H;
    const __nv_bfloat16* __restrict__ Wb = g_Wb[widx];

    int row0 = blockIdx.x * 128;
    int tid = threadIdx.x;
    int wid = tid >> 5, lane = tid & 31;
    int gid = lane >> 2, tig = lane & 3;
    int wm = wid >> 2, wn = wid & 3;
    int mbase = wm * 64, nbase = wn * 32;

    float acc[4][4][4];
#pragma unroll
    for (int a = 0; a < 4; a++)
#pragma unroll
        for (int b = 0; b < 4; b++)
#pragma unroll
            for (int c = 0; c < 4; c++) acc[a][b][c] = 0.0f;

    for (int kc = 0; kc < 128; kc += 64) {
        if (useXf) {
#pragma unroll
            for (int p = 0; p < 8; p++) {
                int f = tid + p * 256;
                int r = f >> 4, c4 = f & 15;
                float4 v = make_float4(0.f, 0.f, 0.f, 0.f);
                int gr = row0 + r;
                if (gr < n) v = *(const float4*)&Xf[(size_t)gr * CD + kc + c4 * 4];
                *(uint2*)&Xs[r][c4 * 4] =
                    make_uint2(pack_bf16x2(v.x, v.y), pack_bf16x2(v.z, v.w));
            }
        } else {
#pragma unroll
            for (int p = 0; p < 4; p++) {
                int f = tid + p * 256;
                int r = f >> 3, c8 = f & 7;
                uint4 v = make_uint4(0, 0, 0, 0);
                int gr = row0 + r;
                if (gr < n) v = *(const uint4*)&Hb[(size_t)gr * CD + kc + c8 * 8];
                *(uint4*)&Xs[r][c8 * 8] = v;
            }
        }
#pragma unroll
        for (int p = 0; p < 4; p++) {
            int f = tid + p * 256;
            int r = f >> 3, c8 = f & 7;
            *(uint4*)&Ws[r][c8 * 8] = *(const uint4*)&Wb[(size_t)r * CD + kc + c8 * 8];
        }
        __syncthreads();

#pragma unroll
        for (int kb = 0; kb < 64; kb += 16) {
            unsigned int af[4][4];
#pragma unroll
            for (int mt = 0; mt < 4; mt++) {
                int r = mbase + mt * 16 + gid;
                af[mt][0] = *(const unsigned int*)&Xs[r][kb + 2 * tig];
                af[mt][1] = *(const unsigned int*)&Xs[r + 8][kb + 2 * tig];
                af[mt][2] = *(const unsigned int*)&Xs[r][kb + 2 * tig + 8];
                af[mt][3] = *(const unsigned int*)&Xs[r + 8][kb + 2 * tig + 8];
            }
            unsigned int bfr[4][2];
#pragma unroll
            for (int nt = 0; nt < 4; nt++) {
                int cn = nbase + nt * 8 + gid;
                bfr[nt][0] = *(const unsigned int*)&Ws[cn][kb + 2 * tig];
                bfr[nt][1] = *(const unsigned int*)&Ws[cn][kb + 2 * tig + 8];
            }
#pragma unroll
            for (int mt = 0; mt < 4; mt++)
#pragma unroll
                for (int nt = 0; nt < 4; nt++) {
                    asm("mma.sync.aligned.m16n8k16.row.col.f32.bf16.bf16.f32 "
                        "{%0,%1,%2,%3}, {%4,%5,%6,%7}, {%8,%9}, {%0,%1,%2,%3};"
                        : "+f"(acc[mt][nt][0]), "+f"(acc[mt][nt][1]),
                          "+f"(acc[mt][nt][2]), "+f"(acc[mt][nt][3])
                        : "r"(af[mt][0]), "r"(af[mt][1]), "r"(af[mt][2]), "r"(af[mt][3]),
                          "r"(bfr[nt][0]), "r"(bfr[nt][1]));
                }
        }
        __syncthreads();
    }

    __nv_bfloat16* Pb = (__nv_bfloat16*)g_P;
#pragma unroll
    for (int mt = 0; mt < 4; mt++) {
        int r0 = row0 + mbase + mt * 16 + gid;
        int r1 = r0 + 8;
        if (outF32) {
#pragma unroll
            for (int nt = 0; nt < 4; nt++) {
                int cn = nbase + nt * 8 + tig * 2;
                if (r0 < n)
                    *(float2*)&g_P[(size_t)r0 * CD + cn] =
                        make_float2(acc[mt][nt][0], acc[mt][nt][1]);
                if (r1 < n)
                    *(float2*)&g_P[(size_t)r1 * CD + cn] =
                        make_float2(acc[mt][nt][2], acc[mt][nt][3]);
            }
        } else {
            float s0 = (r0 < n) ? g_dis[r0] : 0.0f;
            float s1 = (r1 < n) ? g_dis[r1] : 0.0f;
#pragma unroll
            for (int nt = 0; nt < 4; nt++) {
                int cn = nbase + nt * 8 + tig * 2;
                if (r0 < n)
                    *(unsigned int*)&Pb[(size_t)r0 * CD + cn] =
                        pack_bf16x2(acc[mt][nt][0] * s0, acc[mt][nt][1] * s0);
                if (r1 < n)
                    *(unsigned int*)&Pb[(size_t)r1 * CD + cn] =
                        pack_bf16x2(acc[mt][nt][2] * s1, acc[mt][nt][3] * s1);
            }
        }
    }
}

// ---------------- gather (champion-exact) ----------------
__global__ void k_gather(const float* __restrict__ bias, int n) {
    int w = (blockIdx.x * blockDim.x + threadIdx.x) >> 5;
    if (w >= n) return;
    int lane = threadIdx.x & 31;

    const uint2* __restrict__ P2 = (const uint2*)g_P;
    uint2 sv = P2[(size_t)w * 32 + lane];
    float ax = __low2float(*(__nv_bfloat162*)&sv.x);
    float ay = __high2float(*(__nv_bfloat162*)&sv.x);
    float az = __low2float(*(__nv_bfloat162*)&sv.y);
    float aw = __high2float(*(__nv_bfloat162*)&sv.y);

    int o = g_off[w];
    int c = g_cnt[w];
    int j = 0;
    for (; j + 2 <= c; j += 2) {
        int r0 = g_bkt[o + j];
        int r1 = g_bkt[o + j + 1];
        uint2 v0 = P2[(size_t)r0 * 32 + lane];
        uint2 v1 = P2[(size_t)r1 * 32 + lane];
        ax += __low2float(*(__nv_bfloat162*)&v0.x);
        ay += __high2float(*(__nv_bfloat162*)&v0.x);
        az += __low2float(*(__nv_bfloat162*)&v0.y);
        aw += __high2float(*(__nv_bfloat162*)&v0.y);
        ax += __low2float(*(__nv_bfloat162*)&v1.x);
        ay += __high2float(*(__nv_bfloat162*)&v1.x);
        az += __low2float(*(__nv_bfloat162*)&v1.y);
        aw += __high2float(*(__nv_bfloat162*)&v1.y);
    }
    if (j < c) {
        int r0 = g_bkt[o + j];
        uint2 v0 = P2[(size_t)r0 * 32 + lane];
        ax += __low2float(*(__nv_bfloat162*)&v0.x);
        ay += __high2float(*(__nv_bfloat162*)&v0.x);
        az += __low2float(*(__nv_bfloat162*)&v0.y);
        aw += __high2float(*(__nv_bfloat162*)&v0.y);
    }

    float s = g_dis[w];
    float4 b = *(const float4*)&bias[lane * 4];
    float ox = fmaxf(fmaf(ax, s, b.x), 0.0f);
    float oy = fmaxf(fmaf(ay, s, b.y), 0.0f);
    float oz = fmaxf(fmaf(az, s, b.z), 0.0f);
    float ow = fmaxf(fmaf(aw, s, b.w), 0.0f);
    ((uint2*)g_H)[(size_t)w * 32 + lane] =
        make_uint2(pack_bf16x2(ox, oy), pack_bf16x2(oz, ow));
}

// ---------------- log_softmax (fp32) ----------------
__global__ void k_logsoftmax(const float* __restrict__ bl, float* __restrict__ out, int n) {
    int w = (blockIdx.x * blockDim.x + threadIdx.x) >> 5;
    if (w >= n) return;
    int lane = threadIdx.x & 31;

    float4 v = *(const float4*)&g_P[(size_t)w * CD + lane * 4];
    float4 b = *(const float4*)&bl[lane * 4];
    v.x += b.x; v.y += b.y; v.z += b.z; v.w += b.w;

    float m = fmaxf(fmaxf(v.x, v.y), fmaxf(v.z, v.w));
#pragma unroll
    for (int d = 16; d; d >>= 1) m = fmaxf(m, __shfl_xor_sync(0xFFFFFFFFu, m, d));

    float s = expf(v.x - m) + expf(v.y - m) + expf(v.z - m) + expf(v.w - m);
#pragma unroll
    for (int d = 16; d; d >>= 1) s += __shfl_xor_sync(0xFFFFFFFFu, s, d);

    float l = m + logf(s);
    float4 o = make_float4(v.x - l, v.y - l, v.z - l, v.w - l);
    *(float4*)&out[(size_t)w * CD + lane * 4] = o;
}

// ---------------- launch (champion-exact schedule) ----------------
extern "C" void kernel_launch(void* const* d_in, const int* in_sizes, int n_in,
                              void* d_out, int out_size) {
    const float* x  = (const float*)d_in[0];
    const int*   ei = (const int*)d_in[1];
    const float* W1 = (const float*)d_in[2];
    const float* b1 = (const float*)d_in[3];
    const float* W2 = (const float*)d_in[4];
    const float* b2 = (const float*)d_in[5];
    const float* Wl = (const float*)d_in[6];
    const float* bl = (const float*)d_in[7];

    int n = in_sizes[0] / CD;
    int E = in_sizes[1] / 2;
    const int* row = ei;
    const int* col = ei + E;

    int nb256 = (n + 255) / 256;
    int nbScan = (n + 1023) / 1024;
    int gatherB = (n + 7) / 8;
    int gemmB = (n + 127) / 128;

    // weights (independent of everything else)
    k_cvtW3<<<192, 256>>>(W1, W2, Wl);

    // degree + bucketing
    k_zero_cnt<<<nb256, 256>>>(n);
    k_count<<<2048, 256>>>(col, E);
    k_dis<<<nb256, 256>>>(n);
    k_scan1<<<nbScan, 1024>>>(n);
    k_scan2<<<1, 128>>>(nbScan);
    k_scan3<<<nb256, 256>>>(n);
    k_fill<<<2048, 256>>>(row, col, E);

    // conv1
    k_gemm_bf16<<<gemmB, 256>>>(x, 1, 0, 0, n);
    k_gather<<<gatherB, 256>>>(b1, n);

    // conv2
    k_gemm_bf16<<<gemmB, 256>>>(nullptr, 0, 1, 0, n);
    k_gather<<<gatherB, 256>>>(b2, n);

    // linear (fp32 out) + log_softmax
    k_gemm_bf16<<<gemmB, 256>>>(nullptr, 0, 2, 1, n);
    k_logsoftmax<<<gatherB, 256>>>(bl, (float*)d_out, n);
}

// round 13
// speedup vs baseline: 1.0161x; 1.0161x over previous
#include <cuda_runtime.h>
#include <cuda_bf16.h>
#include <stdint.h>
#include <math.h>

#define CD 128
#define NMAX 100352
#define EMAX 1700000

// ---------------- device scratch ----------------
__device__ __align__(16) float g_P[(size_t)NMAX * CD];      // fp32 logits OR bf16 conv out
__device__ __align__(16) float g_H[(size_t)NMAX * CD / 2];  // bf16 hidden
__device__ float g_dis[NMAX];
__device__ int   g_cnt[NMAX];
__device__ int   g_off[NMAX];
__device__ int   g_cur[NMAX];
__device__ int   g_bkt[EMAX];
__device__ int   g_part[128];
__device__ __align__(16) __nv_bfloat16 g_Wb[3][CD * CD];    // bf16 W[c_out][c_in]

__device__ __forceinline__ unsigned int pack_bf16x2(float lo, float hi) {
    unsigned int r;
    asm("cvt.rn.bf16x2.f32 %0, %1, %2;" : "=r"(r) : "f"(hi), "f"(lo));
    return r;
}

// ---------------- small structural kernels ----------------
__global__ void k_zero_cnt(int n) {
    int i = blockIdx.x * blockDim.x + threadIdx.x;
    if (i < n) g_cnt[i] = 0;
}

__global__ void k_count(const int* __restrict__ col, int E) {
    int E2 = E >> 1;
    const int2* __restrict__ c2 = (const int2*)col;
    for (int e = blockIdx.x * blockDim.x + threadIdx.x; e < E2;
         e += gridDim.x * blockDim.x) {
        int2 c = c2[e];
        atomicAdd(&g_cnt[c.x], 1);
        atomicAdd(&g_cnt[c.y], 1);
    }
    if ((E & 1) && blockIdx.x == 0 && threadIdx.x == 0)
        atomicAdd(&g_cnt[col[E - 1]], 1);
}

__global__ void k_dis(int n) {
    int i = blockIdx.x * blockDim.x + threadIdx.x;
    if (i < n) g_dis[i] = rsqrtf((float)g_cnt[i] + 1.0f);
}

__global__ void k_scan1(int n) {
    __shared__ int wsum[32];
    int tid = threadIdx.x;
    int lane = tid & 31, wid = tid >> 5;
    int i = blockIdx.x * 1024 + tid;
    int x = (i < n) ? g_cnt[i] : 0;
    int v = x;
#pragma unroll
    for (int d = 1; d < 32; d <<= 1) {
        int t = __shfl_up_sync(0xFFFFFFFFu, v, d);
        if (lane >= d) v += t;
    }
    if (lane == 31) wsum[wid] = v;
    __syncthreads();
    if (wid == 0) {
        int w = wsum[lane];
#pragma unroll
        for (int d = 1; d < 32; d <<= 1) {
            int t = __shfl_up_sync(0xFFFFFFFFu, w, d);
            if (lane >= d) w += t;
        }
        wsum[lane] = w;
    }
    __syncthreads();
    int base = (wid > 0) ? wsum[wid - 1] : 0;
    if (i < n) g_off[i] = base + v - x;
    if (tid == 1023) g_part[blockIdx.x] = wsum[31];
}

__global__ void k_scan2(int nb) {
    __shared__ int s[128];
    int tid = threadIdx.x;
    int x = (tid < nb) ? g_part[tid] : 0;
    s[tid] = x;
    __syncthreads();
    for (int d = 1; d < 128; d <<= 1) {
        int t = (tid >= d) ? s[tid - d] : 0;
        __syncthreads();
        s[tid] += t;
        __syncthreads();
    }
    if (tid < nb) g_part[tid] = s[tid] - x;
}

__global__ void k_scan3(int n) {
    int i = blockIdx.x * blockDim.x + threadIdx.x;
    if (i < n) {
        int v = g_off[i] + g_part[i >> 10];
        g_off[i] = v;
        g_cur[i] = v;
    }
}

__global__ void k_fill(const int* __restrict__ row, const int* __restrict__ col, int E) {
    int E2 = E >> 1;
    const int2* __restrict__ r2 = (const int2*)row;
    const int2* __restrict__ c2 = (const int2*)col;
    for (int e = blockIdx.x * blockDim.x + threadIdx.x; e < E2;
         e += gridDim.x * blockDim.x) {
        int2 c = c2[e];
        int2 r = r2[e];
        int p0 = atomicAdd(&g_cur[c.x], 1);
        g_bkt[p0] = r.x;
        int p1 = atomicAdd(&g_cur[c.y], 1);
        g_bkt[p1] = r.y;
    }
    if ((E & 1) && blockIdx.x == 0 && threadIdx.x == 0) {
        int p = atomicAdd(&g_cur[col[E - 1]], 1);
        g_bkt[p] = row[E - 1];
    }
}

__global__ void k_cvtW3(const float* __restrict__ W1, const float* __restrict__ W2,
                        const float* __restrict__ Wl) {
    int i = blockIdx.x * 256 + threadIdx.x;   // 192 blocks
    int which = i >> 14, j = i & 16383;
    const float* W = (which == 0) ? W1 : (which == 1) ? W2 : Wl;
    g_Wb[which][j] = __float2bfloat16(W[j]);
}

// scale bf16 P rows by dis: P[i][*] *= dis[i]  (uint4 = 8 bf16 per thread)
__global__ void k_scaleP(int n) {
    int i = blockIdx.x * blockDim.x + threadIdx.x;   // uint4 index
    int total = n * 16;                              // 16 uint4 per row
    if (i >= total) return;
    int rowi = i >> 4;
    float s = g_dis[rowi];
    uint4* P4 = (uint4*)g_P;
    uint4 v = P4[i];
    uint32_t o[4];
#pragma unroll
    for (int q = 0; q < 4; q++) {
        uint32_t u = (q == 0) ? v.x : (q == 1) ? v.y : (q == 2) ? v.z : v.w;
        __nv_bfloat162 b = *(__nv_bfloat162*)&u;
        o[q] = pack_bf16x2(__low2float(b) * s, __high2float(b) * s);
    }
    P4[i] = make_uint4(o[0], o[1], o[2], o[3]);
}

// ---------------- bf16 tensor-core GEMM ----------------------------------
// P[i][c] = (useDis? dis[i] : 1) * sum_k X[i][k] * W[c][k]; 128x128 tile, m16n8k16.
__global__ void __launch_bounds__(256)
k_gemm_bf16(const float* __restrict__ Xf, int useXf, int widx, int useDis, int outF32,
            int n) {
    __shared__ __align__(16) __nv_bfloat16 Xs[128][72];
    __shared__ __align__(16) __nv_bfloat16 Ws[128][72];

    const __nv_bfloat16* __restrict__ Hb = (const __nv_bfloat16*)g_H;
    const __nv_bfloat16* __restrict__ Wb = g_Wb[widx];

    int row0 = blockIdx.x * 128;
    int tid = threadIdx.x;
    int wid = tid >> 5, lane = tid & 31;
    int gid = lane >> 2, tig = lane & 3;
    int wm = wid >> 2, wn = wid & 3;
    int mbase = wm * 64, nbase = wn * 32;

    float acc[4][4][4];
#pragma unroll
    for (int a = 0; a < 4; a++)
#pragma unroll
        for (int b = 0; b < 4; b++)
#pragma unroll
            for (int c = 0; c < 4; c++) acc[a][b][c] = 0.0f;

    for (int kc = 0; kc < 128; kc += 64) {
        if (useXf) {
#pragma unroll
            for (int p = 0; p < 8; p++) {
                int f = tid + p * 256;
                int r = f >> 4, c4 = f & 15;
                float4 v = make_float4(0.f, 0.f, 0.f, 0.f);
                int gr = row0 + r;
                if (gr < n) v = *(const float4*)&Xf[(size_t)gr * CD + kc + c4 * 4];
                *(uint2*)&Xs[r][c4 * 4] =
                    make_uint2(pack_bf16x2(v.x, v.y), pack_bf16x2(v.z, v.w));
            }
        } else {
#pragma unroll
            for (int p = 0; p < 4; p++) {
                int f = tid + p * 256;
                int r = f >> 3, c8 = f & 7;
                uint4 v = make_uint4(0, 0, 0, 0);
                int gr = row0 + r;
                if (gr < n) v = *(const uint4*)&Hb[(size_t)gr * CD + kc + c8 * 8];
                *(uint4*)&Xs[r][c8 * 8] = v;
            }
        }
#pragma unroll
        for (int p = 0; p < 4; p++) {
            int f = tid + p * 256;
            int r = f >> 3, c8 = f & 7;
            *(uint4*)&Ws[r][c8 * 8] = *(const uint4*)&Wb[(size_t)r * CD + kc + c8 * 8];
        }
        __syncthreads();

#pragma unroll
        for (int kb = 0; kb < 64; kb += 16) {
            unsigned int af[4][4];
#pragma unroll
            for (int mt = 0; mt < 4; mt++) {
                int r = mbase + mt * 16 + gid;
                af[mt][0] = *(const unsigned int*)&Xs[r][kb + 2 * tig];
                af[mt][1] = *(const unsigned int*)&Xs[r + 8][kb + 2 * tig];
                af[mt][2] = *(const unsigned int*)&Xs[r][kb + 2 * tig + 8];
                af[mt][3] = *(const unsigned int*)&Xs[r + 8][kb + 2 * tig + 8];
            }
            unsigned int bfr[4][2];
#pragma unroll
            for (int nt = 0; nt < 4; nt++) {
                int cn = nbase + nt * 8 + gid;
                bfr[nt][0] = *(const unsigned int*)&Ws[cn][kb + 2 * tig];
                bfr[nt][1] = *(const unsigned int*)&Ws[cn][kb + 2 * tig + 8];
            }
#pragma unroll
            for (int mt = 0; mt < 4; mt++)
#pragma unroll
                for (int nt = 0; nt < 4; nt++) {
                    asm("mma.sync.aligned.m16n8k16.row.col.f32.bf16.bf16.f32 "
                        "{%0,%1,%2,%3}, {%4,%5,%6,%7}, {%8,%9}, {%0,%1,%2,%3};"
                        : "+f"(acc[mt][nt][0]), "+f"(acc[mt][nt][1]),
                          "+f"(acc[mt][nt][2]), "+f"(acc[mt][nt][3])
                        : "r"(af[mt][0]), "r"(af[mt][1]), "r"(af[mt][2]), "r"(af[mt][3]),
                          "r"(bfr[nt][0]), "r"(bfr[nt][1]));
                }
        }
        __syncthreads();
    }

    __nv_bfloat16* Pb = (__nv_bfloat16*)g_P;
#pragma unroll
    for (int mt = 0; mt < 4; mt++) {
        int r0 = row0 + mbase + mt * 16 + gid;
        int r1 = r0 + 8;
        if (outF32) {
#pragma unroll
            for (int nt = 0; nt < 4; nt++) {
                int cn = nbase + nt * 8 + tig * 2;
                if (r0 < n)
                    *(float2*)&g_P[(size_t)r0 * CD + cn] =
                        make_float2(acc[mt][nt][0], acc[mt][nt][1]);
                if (r1 < n)
                    *(float2*)&g_P[(size_t)r1 * CD + cn] =
                        make_float2(acc[mt][nt][2], acc[mt][nt][3]);
            }
        } else {
            float s0 = 1.0f, s1 = 1.0f;
            if (useDis) {
                s0 = (r0 < n) ? g_dis[r0] : 0.0f;
                s1 = (r1 < n) ? g_dis[r1] : 0.0f;
            }
#pragma unroll
            for (int nt = 0; nt < 4; nt++) {
                int cn = nbase + nt * 8 + tig * 2;
                if (r0 < n)
                    *(unsigned int*)&Pb[(size_t)r0 * CD + cn] =
                        pack_bf16x2(acc[mt][nt][0] * s0, acc[mt][nt][1] * s0);
                if (r1 < n)
                    *(unsigned int*)&Pb[(size_t)r1 * CD + cn] =
                        pack_bf16x2(acc[mt][nt][2] * s1, acc[mt][nt][3] * s1);
            }
        }
    }
}

// ---------------- gather (champion-exact) ----------------
__global__ void k_gather(const float* __restrict__ bias, int n) {
    int w = (blockIdx.x * blockDim.x + threadIdx.x) >> 5;
    if (w >= n) return;
    int lane = threadIdx.x & 31;

    const uint2* __restrict__ P2 = (const uint2*)g_P;
    uint2 sv = P2[(size_t)w * 32 + lane];
    float ax = __low2float(*(__nv_bfloat162*)&sv.x);
    float ay = __high2float(*(__nv_bfloat162*)&sv.x);
    float az = __low2float(*(__nv_bfloat162*)&sv.y);
    float aw = __high2float(*(__nv_bfloat162*)&sv.y);

    int o = g_off[w];
    int c = g_cnt[w];
    int j = 0;
    for (; j + 2 <= c; j += 2) {
        int r0 = g_bkt[o + j];
        int r1 = g_bkt[o + j + 1];
        uint2 v0 = P2[(size_t)r0 * 32 + lane];
        uint2 v1 = P2[(size_t)r1 * 32 + lane];
        ax += __low2float(*(__nv_bfloat162*)&v0.x);
        ay += __high2float(*(__nv_bfloat162*)&v0.x);
        az += __low2float(*(__nv_bfloat162*)&v0.y);
        aw += __high2float(*(__nv_bfloat162*)&v0.y);
        ax += __low2float(*(__nv_bfloat162*)&v1.x);
        ay += __high2float(*(__nv_bfloat162*)&v1.x);
        az += __low2float(*(__nv_bfloat162*)&v1.y);
        aw += __high2float(*(__nv_bfloat162*)&v1.y);
    }
    if (j < c) {
        int r0 = g_bkt[o + j];
        uint2 v0 = P2[(size_t)r0 * 32 + lane];
        ax += __low2float(*(__nv_bfloat162*)&v0.x);
        ay += __high2float(*(__nv_bfloat162*)&v0.x);
        az += __low2float(*(__nv_bfloat162*)&v0.y);
        aw += __high2float(*(__nv_bfloat162*)&v0.y);
    }

    float s = g_dis[w];
    float4 b = *(const float4*)&bias[lane * 4];
    float ox = fmaxf(fmaf(ax, s, b.x), 0.0f);
    float oy = fmaxf(fmaf(ay, s, b.y), 0.0f);
    float oz = fmaxf(fmaf(az, s, b.z), 0.0f);
    float ow = fmaxf(fmaf(aw, s, b.w), 0.0f);
    ((uint2*)g_H)[(size_t)w * 32 + lane] =
        make_uint2(pack_bf16x2(ox, oy), pack_bf16x2(oz, ow));
}

// ---------------- log_softmax (fp32) ----------------
__global__ void k_logsoftmax(const float* __restrict__ bl, float* __restrict__ out, int n) {
    int w = (blockIdx.x * blockDim.x + threadIdx.x) >> 5;
    if (w >= n) return;
    int lane = threadIdx.x & 31;

    float4 v = *(const float4*)&g_P[(size_t)w * CD + lane * 4];
    float4 b = *(const float4*)&bl[lane * 4];
    v.x += b.x; v.y += b.y; v.z += b.z; v.w += b.w;

    float m = fmaxf(fmaxf(v.x, v.y), fmaxf(v.z, v.w));
#pragma unroll
    for (int d = 16; d; d >>= 1) m = fmaxf(m, __shfl_xor_sync(0xFFFFFFFFu, m, d));

    float s = expf(v.x - m) + expf(v.y - m) + expf(v.z - m) + expf(v.w - m);
#pragma unroll
    for (int d = 16; d; d >>= 1) s += __shfl_xor_sync(0xFFFFFFFFu, s, d);

    float l = m + logf(s);
    float4 o = make_float4(v.x - l, v.y - l, v.z - l, v.w - l);
    *(float4*)&out[(size_t)w * CD + lane * 4] = o;
}

// ---------------- launch (forked graph: preproc ∥ conv1 GEMM) ----------------
extern "C" void kernel_launch(void* const* d_in, const int* in_sizes, int n_in,
                              void* d_out, int out_size) {
    const float* x  = (const float*)d_in[0];
    const int*   ei = (const int*)d_in[1];
    const float* W1 = (const float*)d_in[2];
    const float* b1 = (const float*)d_in[3];
    const float* W2 = (const float*)d_in[4];
    const float* b2 = (const float*)d_in[5];
    const float* Wl = (const float*)d_in[6];
    const float* bl = (const float*)d_in[7];

    int n = in_sizes[0] / CD;
    int E = in_sizes[1] / 2;
    const int* row = ei;
    const int* col = ei + E;

    int nb256 = (n + 255) / 256;
    int nbScan = (n + 1023) / 1024;
    int gatherB = (n + 7) / 8;
    int gemmB = (n + 127) / 128;
    int scalePB = (n * 16 + 255) / 256;

    // one-time host objects (created on first/correctness call; capture call reuses)
    static cudaStream_t s1 = nullptr;
    static cudaEvent_t evFork = nullptr, evJoin = nullptr;
    if (s1 == nullptr) {
        cudaStreamCreateWithFlags(&s1, cudaStreamNonBlocking);
        cudaEventCreateWithFlags(&evFork, cudaEventDisableTiming);
        cudaEventCreateWithFlags(&evJoin, cudaEventDisableTiming);
    }

    // weights first (GEMM1 needs W1)
    k_cvtW3<<<192, 256>>>(W1, W2, Wl);

    // fork: preproc on s1, conv1 GEMM (dis-free) on default stream
    cudaEventRecord(evFork, 0);
    cudaStreamWaitEvent(s1, evFork, 0);

    k_zero_cnt<<<nb256, 256, 0, s1>>>(n);
    k_count<<<2048, 256, 0, s1>>>(col, E);
    k_dis<<<nb256, 256, 0, s1>>>(n);
    k_scan1<<<nbScan, 1024, 0, s1>>>(n);
    k_scan2<<<1, 128, 0, s1>>>(nbScan);
    k_scan3<<<nb256, 256, 0, s1>>>(n);
    k_fill<<<2048, 256, 0, s1>>>(row, col, E);

    k_gemm_bf16<<<gemmB, 256>>>(x, 1, 0, 0, 0, n);   // raw conv1 output

    // join
    cudaEventRecord(evJoin, s1);
    cudaStreamWaitEvent(0, evJoin, 0);

    // apply dis to conv1 output, then aggregate
    k_scaleP<<<scalePB, 256>>>(n);
    k_gather<<<gatherB, 256>>>(b1, n);

    // conv2 (dis pre-scaled in epilogue)
    k_gemm_bf16<<<gemmB, 256>>>(nullptr, 0, 1, 1, 0, n);
    k_gather<<<gatherB, 256>>>(b2, n);

    // linear (fp32 out) + log_softmax
    k_gemm_bf16<<<gemmB, 256>>>(nullptr, 0, 2, 0, 1, n);
    k_logsoftmax<<<gatherB, 256>>>(bl, (float*)d_out, n);
}

// round 14
// speedup vs baseline: 1.1728x; 1.1542x over previous
#include <cuda_runtime.h>
#include <cuda_bf16.h>
#include <stdint.h>
#include <math.h>

#define CD 128
#define NMAX 100352
#define EMAX 1700000
#define GSTRIDE 136
#define GEMM_SMEM (2 * 128 * GSTRIDE * 2)   // 69632 bytes

// ---------------- device scratch ----------------
__device__ __align__(16) float g_P[(size_t)NMAX * CD];      // fp32 logits OR bf16 conv out
__device__ __align__(16) float g_H[(size_t)NMAX * CD / 2];  // bf16 hidden
__device__ float g_dis[NMAX];
__device__ int   g_cnt[NMAX];
__device__ int   g_off[NMAX];
__device__ int   g_cur[NMAX];
__device__ int   g_bkt[EMAX];
__device__ int   g_part[128];
__device__ __align__(16) __nv_bfloat16 g_Wb[3][CD * CD];    // bf16 W[c_out][c_in]

__device__ __forceinline__ unsigned int pack_bf16x2(float lo, float hi) {
    unsigned int r;
    asm("cvt.rn.bf16x2.f32 %0, %1, %2;" : "=r"(r) : "f"(hi), "f"(lo));
    return r;
}

// ---------------- small structural kernels ----------------
__global__ void k_zero_cnt(int n) {
    int i = blockIdx.x * blockDim.x + threadIdx.x;
    if (i < n) g_cnt[i] = 0;
}

__global__ void k_count(const int* __restrict__ col, int E) {
    int E2 = E >> 1;
    const int2* __restrict__ c2 = (const int2*)col;
    for (int e = blockIdx.x * blockDim.x + threadIdx.x; e < E2;
         e += gridDim.x * blockDim.x) {
        int2 c = c2[e];
        atomicAdd(&g_cnt[c.x], 1);
        atomicAdd(&g_cnt[c.y], 1);
    }
    if ((E & 1) && blockIdx.x == 0 && threadIdx.x == 0)
        atomicAdd(&g_cnt[col[E - 1]], 1);
}

__global__ void k_dis(int n) {
    int i = blockIdx.x * blockDim.x + threadIdx.x;
    if (i < n) g_dis[i] = rsqrtf((float)g_cnt[i] + 1.0f);
}

__global__ void k_scan1(int n) {
    __shared__ int wsum[32];
    int tid = threadIdx.x;
    int lane = tid & 31, wid = tid >> 5;
    int i = blockIdx.x * 1024 + tid;
    int x = (i < n) ? g_cnt[i] : 0;
    int v = x;
#pragma unroll
    for (int d = 1; d < 32; d <<= 1) {
        int t = __shfl_up_sync(0xFFFFFFFFu, v, d);
        if (lane >= d) v += t;
    }
    if (lane == 31) wsum[wid] = v;
    __syncthreads();
    if (wid == 0) {
        int w = wsum[lane];
#pragma unroll
        for (int d = 1; d < 32; d <<= 1) {
            int t = __shfl_up_sync(0xFFFFFFFFu, w, d);
            if (lane >= d) w += t;
        }
        wsum[lane] = w;
    }
    __syncthreads();
    int base = (wid > 0) ? wsum[wid - 1] : 0;
    if (i < n) g_off[i] = base + v - x;
    if (tid == 1023) g_part[blockIdx.x] = wsum[31];
}

__global__ void k_scan2(int nb) {
    __shared__ int s[128];
    int tid = threadIdx.x;
    int x = (tid < nb) ? g_part[tid] : 0;
    s[tid] = x;
    __syncthreads();
    for (int d = 1; d < 128; d <<= 1) {
        int t = (tid >= d) ? s[tid - d] : 0;
        __syncthreads();
        s[tid] += t;
        __syncthreads();
    }
    if (tid < nb) g_part[tid] = s[tid] - x;
}

__global__ void k_scan3(int n) {
    int i = blockIdx.x * blockDim.x + threadIdx.x;
    if (i < n) {
        int v = g_off[i] + g_part[i >> 10];
        g_off[i] = v;
        g_cur[i] = v;
    }
}

__global__ void k_fill(const int* __restrict__ row, const int* __restrict__ col, int E) {
    int E2 = E >> 1;
    const int2* __restrict__ r2 = (const int2*)row;
    const int2* __restrict__ c2 = (const int2*)col;
    for (int e = blockIdx.x * blockDim.x + threadIdx.x; e < E2;
         e += gridDim.x * blockDim.x) {
        int2 c = c2[e];
        int2 r = r2[e];
        int p0 = atomicAdd(&g_cur[c.x], 1);
        g_bkt[p0] = r.x;
        int p1 = atomicAdd(&g_cur[c.y], 1);
        g_bkt[p1] = r.y;
    }
    if ((E & 1) && blockIdx.x == 0 && threadIdx.x == 0) {
        int p = atomicAdd(&g_cur[col[E - 1]], 1);
        g_bkt[p] = row[E - 1];
    }
}

__global__ void k_cvtW3(const float* __restrict__ W1, const float* __restrict__ W2,
                        const float* __restrict__ Wl) {
    int i = blockIdx.x * 256 + threadIdx.x;   // 192 blocks
    int which = i >> 14, j = i & 16383;
    const float* W = (which == 0) ? W1 : (which == 1) ? W2 : Wl;
    g_Wb[which][j] = __float2bfloat16(W[j]);
}

// ---------------- bf16 tensor-core GEMM: whole-K tiles, 1 sync ----------------------
// P[i][c] = (useDis? dis[i] : 1) * sum_k X[i][k] * W[c][k]; 128x128x128 per block.
__global__ void __launch_bounds__(256)
k_gemm_bf16(const float* __restrict__ Xf, int useXf, int widx, int useDis, int outF32,
            int n) {
    extern __shared__ __nv_bfloat16 sm[];
    __nv_bfloat16* Xs = sm;                       // [128][GSTRIDE]
    __nv_bfloat16* Ws = sm + 128 * GSTRIDE;       // [128][GSTRIDE]

    const __nv_bfloat16* __restrict__ Hb = (const __nv_bfloat16*)g_H;
    const __nv_bfloat16* __restrict__ Wb = g_Wb[widx];

    int row0 = blockIdx.x * 128;
    int tid = threadIdx.x;
    int wid = tid >> 5, lane = tid & 31;
    int gid = lane >> 2, tig = lane & 3;
    int wm = wid >> 2, wn = wid & 3;
    int mbase = wm * 64, nbase = wn * 32;

    // load whole A tile (128x128)
    if (useXf) {
#pragma unroll
        for (int p = 0; p < 16; p++) {
            int f = tid + p * 256;
            int r = f >> 5, c4 = f & 31;
            float4 v = make_float4(0.f, 0.f, 0.f, 0.f);
            int gr = row0 + r;
            if (gr < n) v = *(const float4*)&Xf[(size_t)gr * CD + c4 * 4];
            *(uint2*)&Xs[r * GSTRIDE + c4 * 4] =
                make_uint2(pack_bf16x2(v.x, v.y), pack_bf16x2(v.z, v.w));
        }
    } else {
#pragma unroll
        for (int p = 0; p < 8; p++) {
            int f = tid + p * 256;
            int r = f >> 4, c8 = f & 15;
            uint4 v = make_uint4(0, 0, 0, 0);
            int gr = row0 + r;
            if (gr < n) v = *(const uint4*)&Hb[(size_t)gr * CD + c8 * 8];
            *(uint4*)&Xs[r * GSTRIDE + c8 * 8] = v;
        }
    }
    // load whole W tile (128x128)
#pragma unroll
    for (int p = 0; p < 8; p++) {
        int f = tid + p * 256;
        int r = f >> 4, c8 = f & 15;
        *(uint4*)&Ws[r * GSTRIDE + c8 * 8] = *(const uint4*)&Wb[(size_t)r * CD + c8 * 8];
    }
    __syncthreads();

    float acc[4][4][4];
#pragma unroll
    for (int a = 0; a < 4; a++)
#pragma unroll
        for (int b = 0; b < 4; b++)
#pragma unroll
            for (int c = 0; c < 4; c++) acc[a][b][c] = 0.0f;

#pragma unroll
    for (int kb = 0; kb < 128; kb += 16) {
        unsigned int af[4][4];
#pragma unroll
        for (int mt = 0; mt < 4; mt++) {
            int r = mbase + mt * 16 + gid;
            af[mt][0] = *(const unsigned int*)&Xs[r * GSTRIDE + kb + 2 * tig];
            af[mt][1] = *(const unsigned int*)&Xs[(r + 8) * GSTRIDE + kb + 2 * tig];
            af[mt][2] = *(const unsigned int*)&Xs[r * GSTRIDE + kb + 2 * tig + 8];
            af[mt][3] = *(const unsigned int*)&Xs[(r + 8) * GSTRIDE + kb + 2 * tig + 8];
        }
        unsigned int bfr[4][2];
#pragma unroll
        for (int nt = 0; nt < 4; nt++) {
            int cn = nbase + nt * 8 + gid;
            bfr[nt][0] = *(const unsigned int*)&Ws[cn * GSTRIDE + kb + 2 * tig];
            bfr[nt][1] = *(const unsigned int*)&Ws[cn * GSTRIDE + kb + 2 * tig + 8];
        }
#pragma unroll
        for (int mt = 0; mt < 4; mt++)
#pragma unroll
            for (int nt = 0; nt < 4; nt++) {
                asm("mma.sync.aligned.m16n8k16.row.col.f32.bf16.bf16.f32 "
                    "{%0,%1,%2,%3}, {%4,%5,%6,%7}, {%8,%9}, {%0,%1,%2,%3};"
                    : "+f"(acc[mt][nt][0]), "+f"(acc[mt][nt][1]),
                      "+f"(acc[mt][nt][2]), "+f"(acc[mt][nt][3])
                    : "r"(af[mt][0]), "r"(af[mt][1]), "r"(af[mt][2]), "r"(af[mt][3]),
                      "r"(bfr[nt][0]), "r"(bfr[nt][1]));
            }
    }

    __nv_bfloat16* Pb = (__nv_bfloat16*)g_P;
#pragma unroll
    for (int mt = 0; mt < 4; mt++) {
        int r0 = row0 + mbase + mt * 16 + gid;
        int r1 = r0 + 8;
        if (outF32) {
#pragma unroll
            for (int nt = 0; nt < 4; nt++) {
                int cn = nbase + nt * 8 + tig * 2;
                if (r0 < n)
                    *(float2*)&g_P[(size_t)r0 * CD + cn] =
                        make_float2(acc[mt][nt][0], acc[mt][nt][1]);
                if (r1 < n)
                    *(float2*)&g_P[(size_t)r1 * CD + cn] =
                        make_float2(acc[mt][nt][2], acc[mt][nt][3]);
            }
        } else {
            float s0 = 1.0f, s1 = 1.0f;
            if (useDis) {
                s0 = (r0 < n) ? g_dis[r0] : 0.0f;
                s1 = (r1 < n) ? g_dis[r1] : 0.0f;
            }
#pragma unroll
            for (int nt = 0; nt < 4; nt++) {
                int cn = nbase + nt * 8 + tig * 2;
                if (r0 < n)
                    *(unsigned int*)&Pb[(size_t)r0 * CD + cn] =
                        pack_bf16x2(acc[mt][nt][0] * s0, acc[mt][nt][1] * s0);
                if (r1 < n)
                    *(unsigned int*)&Pb[(size_t)r1 * CD + cn] =
                        pack_bf16x2(acc[mt][nt][2] * s1, acc[mt][nt][3] * s1);
            }
        }
    }
}

// ---------------- gather (champion-exact) ----------------
__global__ void k_gather(const float* __restrict__ bias, int n) {
    int w = (blockIdx.x * blockDim.x + threadIdx.x) >> 5;
    if (w >= n) return;
    int lane = threadIdx.x & 31;

    const uint2* __restrict__ P2 = (const uint2*)g_P;
    uint2 sv = P2[(size_t)w * 32 + lane];
    float ax = __low2float(*(__nv_bfloat162*)&sv.x);
    float ay = __high2float(*(__nv_bfloat162*)&sv.x);
    float az = __low2float(*(__nv_bfloat162*)&sv.y);
    float aw = __high2float(*(__nv_bfloat162*)&sv.y);

    int o = g_off[w];
    int c = g_cnt[w];
    int j = 0;
    for (; j + 2 <= c; j += 2) {
        int r0 = g_bkt[o + j];
        int r1 = g_bkt[o + j + 1];
        uint2 v0 = P2[(size_t)r0 * 32 + lane];
        uint2 v1 = P2[(size_t)r1 * 32 + lane];
        ax += __low2float(*(__nv_bfloat162*)&v0.x);
        ay += __high2float(*(__nv_bfloat162*)&v0.x);
        az += __low2float(*(__nv_bfloat162*)&v0.y);
        aw += __high2float(*(__nv_bfloat162*)&v0.y);
        ax += __low2float(*(__nv_bfloat162*)&v1.x);
        ay += __high2float(*(__nv_bfloat162*)&v1.x);
        az += __low2float(*(__nv_bfloat162*)&v1.y);
        aw += __high2float(*(__nv_bfloat162*)&v1.y);
    }
    if (j < c) {
        int r0 = g_bkt[o + j];
        uint2 v0 = P2[(size_t)r0 * 32 + lane];
        ax += __low2float(*(__nv_bfloat162*)&v0.x);
        ay += __high2float(*(__nv_bfloat162*)&v0.x);
        az += __low2float(*(__nv_bfloat162*)&v0.y);
        aw += __high2float(*(__nv_bfloat162*)&v0.y);
    }

    float s = g_dis[w];
    float4 b = *(const float4*)&bias[lane * 4];
    float ox = fmaxf(fmaf(ax, s, b.x), 0.0f);
    float oy = fmaxf(fmaf(ay, s, b.y), 0.0f);
    float oz = fmaxf(fmaf(az, s, b.z), 0.0f);
    float ow = fmaxf(fmaf(aw, s, b.w), 0.0f);
    ((uint2*)g_H)[(size_t)w * 32 + lane] =
        make_uint2(pack_bf16x2(ox, oy), pack_bf16x2(oz, ow));
}

// ---------------- log_softmax (fp32) ----------------
__global__ void k_logsoftmax(const float* __restrict__ bl, float* __restrict__ out, int n) {
    int w = (blockIdx.x * blockDim.x + threadIdx.x) >> 5;
    if (w >= n) return;
    int lane = threadIdx.x & 31;

    float4 v = *(const float4*)&g_P[(size_t)w * CD + lane * 4];
    float4 b = *(const float4*)&bl[lane * 4];
    v.x += b.x; v.y += b.y; v.z += b.z; v.w += b.w;

    float m = fmaxf(fmaxf(v.x, v.y), fmaxf(v.z, v.w));
#pragma unroll
    for (int d = 16; d; d >>= 1) m = fmaxf(m, __shfl_xor_sync(0xFFFFFFFFu, m, d));

    float s = expf(v.x - m) + expf(v.y - m) + expf(v.z - m) + expf(v.w - m);
#pragma unroll
    for (int d = 16; d; d >>= 1) s += __shfl_xor_sync(0xFFFFFFFFu, s, d);

    float l = m + logf(s);
    float4 o = make_float4(v.x - l, v.y - l, v.z - l, v.w - l);
    *(float4*)&out[(size_t)w * CD + lane * 4] = o;
}

// ---------------- launch (early-dis fork: scan/fill overlap GEMM1) ----------------
extern "C" void kernel_launch(void* const* d_in, const int* in_sizes, int n_in,
                              void* d_out, int out_size) {
    const float* x  = (const float*)d_in[0];
    const int*   ei = (const int*)d_in[1];
    const float* W1 = (const float*)d_in[2];
    const float* b1 = (const float*)d_in[3];
    const float* W2 = (const float*)d_in[4];
    const float* b2 = (const float*)d_in[5];
    const float* Wl = (const float*)d_in[6];
    const float* bl = (const float*)d_in[7];

    int n = in_sizes[0] / CD;
    int E = in_sizes[1] / 2;
    const int* row = ei;
    const int* col = ei + E;

    int nb256 = (n + 255) / 256;
    int nbScan = (n + 1023) / 1024;
    int gatherB = (n + 7) / 8;
    int gemmB = (n + 127) / 128;

    // one-time host objects / attributes
    static cudaStream_t s1 = nullptr;
    static cudaEvent_t evFork = nullptr, evDis = nullptr, evJoin = nullptr;
    if (s1 == nullptr) {
        cudaFuncSetAttribute(k_gemm_bf16,
                             cudaFuncAttributeMaxDynamicSharedMemorySize, GEMM_SMEM);
        cudaStreamCreateWithFlags(&s1, cudaStreamNonBlocking);
        cudaEventCreateWithFlags(&evFork, cudaEventDisableTiming);
        cudaEventCreateWithFlags(&evDis, cudaEventDisableTiming);
        cudaEventCreateWithFlags(&evJoin, cudaEventDisableTiming);
    }

    // weights first (GEMM1 needs W1)
    k_cvtW3<<<192, 256>>>(W1, W2, Wl);

    // fork: preproc on s1
    cudaEventRecord(evFork, 0);
    cudaStreamWaitEvent(s1, evFork, 0);

    k_zero_cnt<<<nb256, 256, 0, s1>>>(n);
    k_count<<<2048, 256, 0, s1>>>(col, E);
    k_dis<<<nb256, 256, 0, s1>>>(n);
    cudaEventRecord(evDis, s1);              // dis ready early

    k_scan1<<<nbScan, 1024, 0, s1>>>(n);     // rest of preproc overlaps GEMM1
    k_scan2<<<1, 128, 0, s1>>>(nbScan);
    k_scan3<<<nb256, 256, 0, s1>>>(n);
    k_fill<<<2048, 256, 0, s1>>>(row, col, E);
    cudaEventRecord(evJoin, s1);

    // conv1 GEMM (champion dis-scaled epilogue) — waits only for dis
    cudaStreamWaitEvent(0, evDis, 0);
    k_gemm_bf16<<<gemmB, 256, GEMM_SMEM>>>(x, 1, 0, 1, 0, n);

    // gather needs buckets
    cudaStreamWaitEvent(0, evJoin, 0);
    k_gather<<<gatherB, 256>>>(b1, n);

    // conv2
    k_gemm_bf16<<<gemmB, 256, GEMM_SMEM>>>(nullptr, 0, 1, 1, 0, n);
    k_gather<<<gatherB, 256>>>(b2, n);

    // linear (fp32 out) + log_softmax
    k_gemm_bf16<<<gemmB, 256, GEMM_SMEM>>>(nullptr, 0, 2, 0, 1, n);
    k_logsoftmax<<<gatherB, 256>>>(bl, (float*)d_out, n);
}

// round 15
// speedup vs baseline: 1.2332x; 1.0514x over previous
#include <cuda_runtime.h>
#include <cuda_bf16.h>
#include <stdint.h>
#include <math.h>

#define CD 128
#define NMAX 100352
#define EMAX 1700000
#define GSTRIDE 136
#define GEMM_SMEM (2 * 128 * GSTRIDE * 2)   // 69632 bytes

// ---------------- device scratch ----------------
__device__ __align__(16) float g_P[(size_t)NMAX * CD];      // bf16 conv out (cast)
__device__ __align__(16) float g_H[(size_t)NMAX * CD / 2];  // bf16 hidden
__device__ float g_dis[NMAX];
__device__ int   g_cnt[NMAX];
__device__ int   g_off[NMAX];
__device__ int   g_cur[NMAX];
__device__ int   g_bkt[EMAX];
__device__ int   g_part[128];
__device__ __align__(16) __nv_bfloat16 g_Wb[3][CD * CD];    // bf16 W[c_out][c_in]

__device__ __forceinline__ unsigned int pack_bf16x2(float lo, float hi) {
    unsigned int r;
    asm("cvt.rn.bf16x2.f32 %0, %1, %2;" : "=r"(r) : "f"(hi), "f"(lo));
    return r;
}

// ---------------- small structural kernels ----------------
__global__ void k_zero_cnt(int n) {
    int i = blockIdx.x * blockDim.x + threadIdx.x;
    if (i < n) g_cnt[i] = 0;
}

__global__ void k_count(const int* __restrict__ col, int E) {
    int E2 = E >> 1;
    const int2* __restrict__ c2 = (const int2*)col;
    for (int e = blockIdx.x * blockDim.x + threadIdx.x; e < E2;
         e += gridDim.x * blockDim.x) {
        int2 c = c2[e];
        atomicAdd(&g_cnt[c.x], 1);
        atomicAdd(&g_cnt[c.y], 1);
    }
    if ((E & 1) && blockIdx.x == 0 && threadIdx.x == 0)
        atomicAdd(&g_cnt[col[E - 1]], 1);
}

__global__ void k_dis(int n) {
    int i = blockIdx.x * blockDim.x + threadIdx.x;
    if (i < n) g_dis[i] = rsqrtf((float)g_cnt[i] + 1.0f);
}

__global__ void k_scan1(int n) {
    __shared__ int wsum[32];
    int tid = threadIdx.x;
    int lane = tid & 31, wid = tid >> 5;
    int i = blockIdx.x * 1024 + tid;
    int x = (i < n) ? g_cnt[i] : 0;
    int v = x;
#pragma unroll
    for (int d = 1; d < 32; d <<= 1) {
        int t = __shfl_up_sync(0xFFFFFFFFu, v, d);
        if (lane >= d) v += t;
    }
    if (lane == 31) wsum[wid] = v;
    __syncthreads();
    if (wid == 0) {
        int w = wsum[lane];
#pragma unroll
        for (int d = 1; d < 32; d <<= 1) {
            int t = __shfl_up_sync(0xFFFFFFFFu, w, d);
            if (lane >= d) w += t;
        }
        wsum[lane] = w;
    }
    __syncthreads();
    int base = (wid > 0) ? wsum[wid - 1] : 0;
    if (i < n) g_off[i] = base + v - x;
    if (tid == 1023) g_part[blockIdx.x] = wsum[31];
}

__global__ void k_scan2(int nb) {
    __shared__ int s[128];
    int tid = threadIdx.x;
    int x = (tid < nb) ? g_part[tid] : 0;
    s[tid] = x;
    __syncthreads();
    for (int d = 1; d < 128; d <<= 1) {
        int t = (tid >= d) ? s[tid - d] : 0;
        __syncthreads();
        s[tid] += t;
        __syncthreads();
    }
    if (tid < nb) g_part[tid] = s[tid] - x;
}

__global__ void k_scan3(int n) {
    int i = blockIdx.x * blockDim.x + threadIdx.x;
    if (i < n) {
        int v = g_off[i] + g_part[i >> 10];
        g_off[i] = v;
        g_cur[i] = v;
    }
}

__global__ void k_fill(const int* __restrict__ row, const int* __restrict__ col, int E) {
    int E2 = E >> 1;
    const int2* __restrict__ r2 = (const int2*)row;
    const int2* __restrict__ c2 = (const int2*)col;
    for (int e = blockIdx.x * blockDim.x + threadIdx.x; e < E2;
         e += gridDim.x * blockDim.x) {
        int2 c = c2[e];
        int2 r = r2[e];
        int p0 = atomicAdd(&g_cur[c.x], 1);
        g_bkt[p0] = r.x;
        int p1 = atomicAdd(&g_cur[c.y], 1);
        g_bkt[p1] = r.y;
    }
    if ((E & 1) && blockIdx.x == 0 && threadIdx.x == 0) {
        int p = atomicAdd(&g_cur[col[E - 1]], 1);
        g_bkt[p] = row[E - 1];
    }
}

__global__ void k_cvtW3(const float* __restrict__ W1, const float* __restrict__ W2,
                        const float* __restrict__ Wl) {
    int i = blockIdx.x * 256 + threadIdx.x;   // 192 blocks
    int which = i >> 14, j = i & 16383;
    const float* W = (which == 0) ? W1 : (which == 1) ? W2 : Wl;
    g_Wb[which][j] = __float2bfloat16(W[j]);
}

// ---------------- bf16 tensor-core GEMM: whole-K tiles, 1 sync (conv layers) --------
// P(bf16)[i][c] = dis[i] * sum_k X[i][k] * W[c][k]; 128x128x128 per block.
__global__ void __launch_bounds__(256)
k_gemm_bf16(const float* __restrict__ Xf, int useXf, int widx, int n) {
    extern __shared__ __nv_bfloat16 sm[];
    __nv_bfloat16* Xs = sm;                       // [128][GSTRIDE]
    __nv_bfloat16* Ws = sm + 128 * GSTRIDE;       // [128][GSTRIDE]

    const __nv_bfloat16* __restrict__ Hb = (const __nv_bfloat16*)g_H;
    const __nv_bfloat16* __restrict__ Wb = g_Wb[widx];

    int row0 = blockIdx.x * 128;
    int tid = threadIdx.x;
    int wid = tid >> 5, lane = tid & 31;
    int gid = lane >> 2, tig = lane & 3;
    int wm = wid >> 2, wn = wid & 3;
    int mbase = wm * 64, nbase = wn * 32;

    if (useXf) {
#pragma unroll
        for (int p = 0; p < 16; p++) {
            int f = tid + p * 256;
            int r = f >> 5, c4 = f & 31;
            float4 v = make_float4(0.f, 0.f, 0.f, 0.f);
            int gr = row0 + r;
            if (gr < n) v = *(const float4*)&Xf[(size_t)gr * CD + c4 * 4];
            *(uint2*)&Xs[r * GSTRIDE + c4 * 4] =
                make_uint2(pack_bf16x2(v.x, v.y), pack_bf16x2(v.z, v.w));
        }
    } else {
#pragma unroll
        for (int p = 0; p < 8; p++) {
            int f = tid + p * 256;
            int r = f >> 4, c8 = f & 15;
            uint4 v = make_uint4(0, 0, 0, 0);
            int gr = row0 + r;
            if (gr < n) v = *(const uint4*)&Hb[(size_t)gr * CD + c8 * 8];
            *(uint4*)&Xs[r * GSTRIDE + c8 * 8] = v;
        }
    }
#pragma unroll
    for (int p = 0; p < 8; p++) {
        int f = tid + p * 256;
        int r = f >> 4, c8 = f & 15;
        *(uint4*)&Ws[r * GSTRIDE + c8 * 8] = *(const uint4*)&Wb[(size_t)r * CD + c8 * 8];
    }
    __syncthreads();

    float acc[4][4][4];
#pragma unroll
    for (int a = 0; a < 4; a++)
#pragma unroll
        for (int b = 0; b < 4; b++)
#pragma unroll
            for (int c = 0; c < 4; c++) acc[a][b][c] = 0.0f;

#pragma unroll
    for (int kb = 0; kb < 128; kb += 16) {
        unsigned int af[4][4];
#pragma unroll
        for (int mt = 0; mt < 4; mt++) {
            int r = mbase + mt * 16 + gid;
            af[mt][0] = *(const unsigned int*)&Xs[r * GSTRIDE + kb + 2 * tig];
            af[mt][1] = *(const unsigned int*)&Xs[(r + 8) * GSTRIDE + kb + 2 * tig];
            af[mt][2] = *(const unsigned int*)&Xs[r * GSTRIDE + kb + 2 * tig + 8];
            af[mt][3] = *(const unsigned int*)&Xs[(r + 8) * GSTRIDE + kb + 2 * tig + 8];
        }
        unsigned int bfr[4][2];
#pragma unroll
        for (int nt = 0; nt < 4; nt++) {
            int cn = nbase + nt * 8 + gid;
            bfr[nt][0] = *(const unsigned int*)&Ws[cn * GSTRIDE + kb + 2 * tig];
            bfr[nt][1] = *(const unsigned int*)&Ws[cn * GSTRIDE + kb + 2 * tig + 8];
        }
#pragma unroll
        for (int mt = 0; mt < 4; mt++)
#pragma unroll
            for (int nt = 0; nt < 4; nt++) {
                asm("mma.sync.aligned.m16n8k16.row.col.f32.bf16.bf16.f32 "
                    "{%0,%1,%2,%3}, {%4,%5,%6,%7}, {%8,%9}, {%0,%1,%2,%3};"
                    : "+f"(acc[mt][nt][0]), "+f"(acc[mt][nt][1]),
                      "+f"(acc[mt][nt][2]), "+f"(acc[mt][nt][3])
                    : "r"(af[mt][0]), "r"(af[mt][1]), "r"(af[mt][2]), "r"(af[mt][3]),
                      "r"(bfr[nt][0]), "r"(bfr[nt][1]));
            }
    }

    __nv_bfloat16* Pb = (__nv_bfloat16*)g_P;
#pragma unroll
    for (int mt = 0; mt < 4; mt++) {
        int r0 = row0 + mbase + mt * 16 + gid;
        int r1 = r0 + 8;
        float s0 = (r0 < n) ? g_dis[r0] : 0.0f;
        float s1 = (r1 < n) ? g_dis[r1] : 0.0f;
#pragma unroll
        for (int nt = 0; nt < 4; nt++) {
            int cn = nbase + nt * 8 + tig * 2;
            if (r0 < n)
                *(unsigned int*)&Pb[(size_t)r0 * CD + cn] =
                    pack_bf16x2(acc[mt][nt][0] * s0, acc[mt][nt][1] * s0);
            if (r1 < n)
                *(unsigned int*)&Pb[(size_t)r1 * CD + cn] =
                    pack_bf16x2(acc[mt][nt][2] * s1, acc[mt][nt][3] * s1);
        }
    }
}

// ---------------- final layer: whole-K GEMM + bias + log_softmax fused --------------
__global__ void __launch_bounds__(256)
k_gemm_ls(const float* __restrict__ bl, float* __restrict__ out, int widx, int n) {
    extern __shared__ __nv_bfloat16 sm[];
    __nv_bfloat16* Xs = sm;
    __nv_bfloat16* Ws = sm + 128 * GSTRIDE;
    __shared__ float smx[128][4];
    __shared__ float sms[128][4];

    const __nv_bfloat16* __restrict__ Hb = (const __nv_bfloat16*)g_H;
    const __nv_bfloat16* __restrict__ Wb = g_Wb[widx];

    int row0 = blockIdx.x * 128;
    int tid = threadIdx.x;
    int wid = tid >> 5, lane = tid & 31;
    int gid = lane >> 2, tig = lane & 3;
    int wm = wid >> 2, wn = wid & 3;
    int mbase = wm * 64, nbase = wn * 32;

#pragma unroll
    for (int p = 0; p < 8; p++) {
        int f = tid + p * 256;
        int r = f >> 4, c8 = f & 15;
        uint4 v = make_uint4(0, 0, 0, 0);
        int gr = row0 + r;
        if (gr < n) v = *(const uint4*)&Hb[(size_t)gr * CD + c8 * 8];
        *(uint4*)&Xs[r * GSTRIDE + c8 * 8] = v;
    }
#pragma unroll
    for (int p = 0; p < 8; p++) {
        int f = tid + p * 256;
        int r = f >> 4, c8 = f & 15;
        *(uint4*)&Ws[r * GSTRIDE + c8 * 8] = *(const uint4*)&Wb[(size_t)r * CD + c8 * 8];
    }
    __syncthreads();

    float acc[4][4][4];
#pragma unroll
    for (int a = 0; a < 4; a++)
#pragma unroll
        for (int b = 0; b < 4; b++)
#pragma unroll
            for (int c = 0; c < 4; c++) acc[a][b][c] = 0.0f;

#pragma unroll
    for (int kb = 0; kb < 128; kb += 16) {
        unsigned int af[4][4];
#pragma unroll
        for (int mt = 0; mt < 4; mt++) {
            int r = mbase + mt * 16 + gid;
            af[mt][0] = *(const unsigned int*)&Xs[r * GSTRIDE + kb + 2 * tig];
            af[mt][1] = *(const unsigned int*)&Xs[(r + 8) * GSTRIDE + kb + 2 * tig];
            af[mt][2] = *(const unsigned int*)&Xs[r * GSTRIDE + kb + 2 * tig + 8];
            af[mt][3] = *(const unsigned int*)&Xs[(r + 8) * GSTRIDE + kb + 2 * tig + 8];
        }
        unsigned int bfr[4][2];
#pragma unroll
        for (int nt = 0; nt < 4; nt++) {
            int cn = nbase + nt * 8 + gid;
            bfr[nt][0] = *(const unsigned int*)&Ws[cn * GSTRIDE + kb + 2 * tig];
            bfr[nt][1] = *(const unsigned int*)&Ws[cn * GSTRIDE + kb + 2 * tig + 8];
        }
#pragma unroll
        for (int mt = 0; mt < 4; mt++)
#pragma unroll
            for (int nt = 0; nt < 4; nt++) {
                asm("mma.sync.aligned.m16n8k16.row.col.f32.bf16.bf16.f32 "
                    "{%0,%1,%2,%3}, {%4,%5,%6,%7}, {%8,%9}, {%0,%1,%2,%3};"
                    : "+f"(acc[mt][nt][0]), "+f"(acc[mt][nt][1]),
                      "+f"(acc[mt][nt][2]), "+f"(acc[mt][nt][3])
                    : "r"(af[mt][0]), "r"(af[mt][1]), "r"(af[mt][2]), "r"(af[mt][3]),
                      "r"(bfr[nt][0]), "r"(bfr[nt][1]));
            }
    }

    // bias -> logits in registers
    float bv[4][2];
#pragma unroll
    for (int nt = 0; nt < 4; nt++) {
        int cn = nbase + nt * 8 + tig * 2;
        float2 b = *(const float2*)&bl[cn];
        bv[nt][0] = b.x; bv[nt][1] = b.y;
    }
#pragma unroll
    for (int mt = 0; mt < 4; mt++)
#pragma unroll
        for (int nt = 0; nt < 4; nt++) {
            acc[mt][nt][0] += bv[nt][0];
            acc[mt][nt][1] += bv[nt][1];
            acc[mt][nt][2] += bv[nt][0];
            acc[mt][nt][3] += bv[nt][1];
        }

    // pass 1: per-row max over this warp's 32 cols
#pragma unroll
    for (int mt = 0; mt < 4; mt++) {
        float m0 = -1e30f, m1 = -1e30f;
#pragma unroll
        for (int nt = 0; nt < 4; nt++) {
            m0 = fmaxf(m0, fmaxf(acc[mt][nt][0], acc[mt][nt][1]));
            m1 = fmaxf(m1, fmaxf(acc[mt][nt][2], acc[mt][nt][3]));
        }
        m0 = fmaxf(m0, __shfl_xor_sync(0xFFFFFFFFu, m0, 1));
        m0 = fmaxf(m0, __shfl_xor_sync(0xFFFFFFFFu, m0, 2));
        m1 = fmaxf(m1, __shfl_xor_sync(0xFFFFFFFFu, m1, 1));
        m1 = fmaxf(m1, __shfl_xor_sync(0xFFFFFFFFu, m1, 2));
        if (tig == 0) {
            smx[mbase + mt * 16 + gid][wn] = m0;
            smx[mbase + mt * 16 + gid + 8][wn] = m1;
        }
    }
    __syncthreads();

    // pass 2: full max, per-row sum(exp) partials
#pragma unroll
    for (int mt = 0; mt < 4; mt++) {
        int lr0 = mbase + mt * 16 + gid;
        int lr1 = lr0 + 8;
        float M0 = fmaxf(fmaxf(smx[lr0][0], smx[lr0][1]), fmaxf(smx[lr0][2], smx[lr0][3]));
        float M1 = fmaxf(fmaxf(smx[lr1][0], smx[lr1][1]), fmaxf(smx[lr1][2], smx[lr1][3]));
        float s0 = 0.0f, s1 = 0.0f;
#pragma unroll
        for (int nt = 0; nt < 4; nt++) {
            s0 += expf(acc[mt][nt][0] - M0) + expf(acc[mt][nt][1] - M0);
            s1 += expf(acc[mt][nt][2] - M1) + expf(acc[mt][nt][3] - M1);
        }
        s0 += __shfl_xor_sync(0xFFFFFFFFu, s0, 1);
        s0 += __shfl_xor_sync(0xFFFFFFFFu, s0, 2);
        s1 += __shfl_xor_sync(0xFFFFFFFFu, s1, 1);
        s1 += __shfl_xor_sync(0xFFFFFFFFu, s1, 2);
        if (tig == 0) {
            sms[lr0][wn] = s0;
            sms[lr1][wn] = s1;
        }
    }
    __syncthreads();

    // final: out = logit - (M + log(sum))
#pragma unroll
    for (int mt = 0; mt < 4; mt++) {
        int lr0 = mbase + mt * 16 + gid;
        int lr1 = lr0 + 8;
        int r0 = row0 + lr0, r1 = row0 + lr1;
        float M0 = fmaxf(fmaxf(smx[lr0][0], smx[lr0][1]), fmaxf(smx[lr0][2], smx[lr0][3]));
        float M1 = fmaxf(fmaxf(smx[lr1][0], smx[lr1][1]), fmaxf(smx[lr1][2], smx[lr1][3]));
        float l0 = M0 + logf(sms[lr0][0] + sms[lr0][1] + sms[lr0][2] + sms[lr0][3]);
        float l1 = M1 + logf(sms[lr1][0] + sms[lr1][1] + sms[lr1][2] + sms[lr1][3]);
#pragma unroll
        for (int nt = 0; nt < 4; nt++) {
            int cn = nbase + nt * 8 + tig * 2;
            if (r0 < n)
                *(float2*)&out[(size_t)r0 * CD + cn] =
                    make_float2(acc[mt][nt][0] - l0, acc[mt][nt][1] - l0);
            if (r1 < n)
                *(float2*)&out[(size_t)r1 * CD + cn] =
                    make_float2(acc[mt][nt][2] - l1, acc[mt][nt][3] - l1);
        }
    }
}

// ---------------- gather (champion-exact) ----------------
__global__ void k_gather(const float* __restrict__ bias, int n) {
    int w = (blockIdx.x * blockDim.x + threadIdx.x) >> 5;
    if (w >= n) return;
    int lane = threadIdx.x & 31;

    const uint2* __restrict__ P2 = (const uint2*)g_P;
    uint2 sv = P2[(size_t)w * 32 + lane];
    float ax = __low2float(*(__nv_bfloat162*)&sv.x);
    float ay = __high2float(*(__nv_bfloat162*)&sv.x);
    float az = __low2float(*(__nv_bfloat162*)&sv.y);
    float aw = __high2float(*(__nv_bfloat162*)&sv.y);

    int o = g_off[w];
    int c = g_cnt[w];
    int j = 0;
    for (; j + 2 <= c; j += 2) {
        int r0 = g_bkt[o + j];
        int r1 = g_bkt[o + j + 1];
        uint2 v0 = P2[(size_t)r0 * 32 + lane];
        uint2 v1 = P2[(size_t)r1 * 32 + lane];
        ax += __low2float(*(__nv_bfloat162*)&v0.x);
        ay += __high2float(*(__nv_bfloat162*)&v0.x);
        az += __low2float(*(__nv_bfloat162*)&v0.y);
        aw += __high2float(*(__nv_bfloat162*)&v0.y);
        ax += __low2float(*(__nv_bfloat162*)&v1.x);
        ay += __high2float(*(__nv_bfloat162*)&v1.x);
        az += __low2float(*(__nv_bfloat162*)&v1.y);
        aw += __high2float(*(__nv_bfloat162*)&v1.y);
    }
    if (j < c) {
        int r0 = g_bkt[o + j];
        uint2 v0 = P2[(size_t)r0 * 32 + lane];
        ax += __low2float(*(__nv_bfloat162*)&v0.x);
        ay += __high2float(*(__nv_bfloat162*)&v0.x);
        az += __low2float(*(__nv_bfloat162*)&v0.y);
        aw += __high2float(*(__nv_bfloat162*)&v0.y);
    }

    float s = g_dis[w];
    float4 b = *(const float4*)&bias[lane * 4];
    float ox = fmaxf(fmaf(ax, s, b.x), 0.0f);
    float oy = fmaxf(fmaf(ay, s, b.y), 0.0f);
    float oz = fmaxf(fmaf(az, s, b.z), 0.0f);
    float ow = fmaxf(fmaf(aw, s, b.w), 0.0f);
    ((uint2*)g_H)[(size_t)w * 32 + lane] =
        make_uint2(pack_bf16x2(ox, oy), pack_bf16x2(oz, ow));
}

// ---------------- launch (early-dis fork + fused final layer) ----------------
extern "C" void kernel_launch(void* const* d_in, const int* in_sizes, int n_in,
                              void* d_out, int out_size) {
    const float* x  = (const float*)d_in[0];
    const int*   ei = (const int*)d_in[1];
    const float* W1 = (const float*)d_in[2];
    const float* b1 = (const float*)d_in[3];
    const float* W2 = (const float*)d_in[4];
    const float* b2 = (const float*)d_in[5];
    const float* Wl = (const float*)d_in[6];
    const float* bl = (const float*)d_in[7];

    int n = in_sizes[0] / CD;
    int E = in_sizes[1] / 2;
    const int* row = ei;
    const int* col = ei + E;

    int nb256 = (n + 255) / 256;
    int nbScan = (n + 1023) / 1024;
    int gatherB = (n + 7) / 8;
    int gemmB = (n + 127) / 128;

    static cudaStream_t s1 = nullptr;
    static cudaEvent_t evFork = nullptr, evDis = nullptr, evJoin = nullptr;
    if (s1 == nullptr) {
        cudaFuncSetAttribute(k_gemm_bf16,
                             cudaFuncAttributeMaxDynamicSharedMemorySize, GEMM_SMEM);
        cudaFuncSetAttribute(k_gemm_ls,
                             cudaFuncAttributeMaxDynamicSharedMemorySize, GEMM_SMEM);
        cudaStreamCreateWithFlags(&s1, cudaStreamNonBlocking);
        cudaEventCreateWithFlags(&evFork, cudaEventDisableTiming);
        cudaEventCreateWithFlags(&evDis, cudaEventDisableTiming);
        cudaEventCreateWithFlags(&evJoin, cudaEventDisableTiming);
    }

    // weights first (GEMM1 needs W1)
    k_cvtW3<<<192, 256>>>(W1, W2, Wl);

    // fork: preproc on s1
    cudaEventRecord(evFork, 0);
    cudaStreamWaitEvent(s1, evFork, 0);

    k_zero_cnt<<<nb256, 256, 0, s1>>>(n);
    k_count<<<2048, 256, 0, s1>>>(col, E);
    k_dis<<<nb256, 256, 0, s1>>>(n);
    cudaEventRecord(evDis, s1);              // dis ready early

    k_scan1<<<nbScan, 1024, 0, s1>>>(n);     // rest of preproc overlaps GEMM1
    k_scan2<<<1, 128, 0, s1>>>(nbScan);
    k_scan3<<<nb256, 256, 0, s1>>>(n);
    k_fill<<<2048, 256, 0, s1>>>(row, col, E);
    cudaEventRecord(evJoin, s1);

    // conv1 GEMM (dis-scaled epilogue) — waits only for dis
    cudaStreamWaitEvent(0, evDis, 0);
    k_gemm_bf16<<<gemmB, 256, GEMM_SMEM>>>(x, 1, 0, n);

    // gather needs buckets
    cudaStreamWaitEvent(0, evJoin, 0);
    k_gather<<<gatherB, 256>>>(b1, n);

    // conv2
    k_gemm_bf16<<<gemmB, 256, GEMM_SMEM>>>(nullptr, 0, 1, n);
    k_gather<<<gatherB, 256>>>(b2, n);

    // linear + log_softmax fused
    k_gemm_ls<<<gemmB, 256, GEMM_SMEM>>>(bl, (float*)d_out, 2, n);
}

// round 16
// speedup vs baseline: 1.2487x; 1.0126x over previous
#include <cuda_runtime.h>
#include <cuda_bf16.h>
#include <stdint.h>
#include <math.h>

#define CD 128
#define NMAX 100352
#define EMAX 1700000
#define GSTRIDE 136
#define GEMM_SMEM (2 * 128 * GSTRIDE * 2)   // 69632 bytes

// ---------------- device scratch ----------------
__device__ __align__(16) float g_P[(size_t)NMAX * CD];      // bf16 conv out (cast)
__device__ __align__(16) float g_H[(size_t)NMAX * CD / 2];  // bf16 hidden
__device__ float g_dis[NMAX];
__device__ int   g_cnt[NMAX];   // INVARIANT: zero at kernel_launch entry (re-zeroed at tail)
__device__ int   g_off[NMAX];
__device__ int   g_cur[NMAX];
__device__ int   g_bkt[EMAX];
__device__ int   g_part[128];
__device__ __align__(16) __nv_bfloat16 g_Wb[3][CD * CD];    // bf16 W[c_out][c_in]

__device__ __forceinline__ unsigned int pack_bf16x2(float lo, float hi) {
    unsigned int r;
    asm("cvt.rn.bf16x2.f32 %0, %1, %2;" : "=r"(r) : "f"(hi), "f"(lo));
    return r;
}

// ---------------- small structural kernels ----------------
__global__ void k_zero_cnt(int n) {
    int i = blockIdx.x * blockDim.x + threadIdx.x;
    if (i < n) g_cnt[i] = 0;
}

__global__ void k_count(const int* __restrict__ col, int E) {
    int E2 = E >> 1;
    const int2* __restrict__ c2 = (const int2*)col;
    for (int e = blockIdx.x * blockDim.x + threadIdx.x; e < E2;
         e += gridDim.x * blockDim.x) {
        int2 c = c2[e];
        atomicAdd(&g_cnt[c.x], 1);
        atomicAdd(&g_cnt[c.y], 1);
    }
    if ((E & 1) && blockIdx.x == 0 && threadIdx.x == 0)
        atomicAdd(&g_cnt[col[E - 1]], 1);
}

// scan pass 1 with dis fused: per-block exclusive scan + block partials
__global__ void k_scan1(int n) {
    __shared__ int wsum[32];
    int tid = threadIdx.x;
    int lane = tid & 31, wid = tid >> 5;
    int i = blockIdx.x * 1024 + tid;
    int x = (i < n) ? g_cnt[i] : 0;
    if (i < n) g_dis[i] = rsqrtf((float)x + 1.0f);
    int v = x;
#pragma unroll
    for (int d = 1; d < 32; d <<= 1) {
        int t = __shfl_up_sync(0xFFFFFFFFu, v, d);
        if (lane >= d) v += t;
    }
    if (lane == 31) wsum[wid] = v;
    __syncthreads();
    if (wid == 0) {
        int w = wsum[lane];
#pragma unroll
        for (int d = 1; d < 32; d <<= 1) {
            int t = __shfl_up_sync(0xFFFFFFFFu, w, d);
            if (lane >= d) w += t;
        }
        wsum[lane] = w;
    }
    __syncthreads();
    int base = (wid > 0) ? wsum[wid - 1] : 0;
    if (i < n) g_off[i] = base + v - x;
    if (tid == 1023) g_part[blockIdx.x] = wsum[31];
}

// scan pass 2+3 merged: each block redundantly scans the <=128 partials
__global__ void k_scan23(int nbScan, int n) {
    __shared__ int s[128];
    int tid = threadIdx.x;
    int lane = tid & 31, w = tid >> 5;

    if (tid < 128) {
        int x = (tid < nbScan) ? g_part[tid] : 0;
        int v = x;
#pragma unroll
        for (int d = 1; d < 32; d <<= 1) {
            int t = __shfl_up_sync(0xFFFFFFFFu, v, d);
            if (lane >= d) v += t;
        }
        s[tid] = v;              // inclusive within warp
    }
    __syncthreads();
    int add = 0;
    if (tid < 128) {
        for (int ww = 0; ww < w; ww++) add += s[ww * 32 + 31];
    }
    __syncthreads();
    if (tid < 128) {
        int x = (tid < nbScan) ? g_part[tid] : 0;
        s[tid] = s[tid] + add - x;   // exclusive prefix of partials
    }
    __syncthreads();

    int i = blockIdx.x * blockDim.x + tid;
    if (i < n) {
        int v = g_off[i] + s[i >> 10];
        g_off[i] = v;
        g_cur[i] = v;
    }
}

__global__ void k_fill(const int* __restrict__ row, const int* __restrict__ col, int E) {
    int E2 = E >> 1;
    const int2* __restrict__ r2 = (const int2*)row;
    const int2* __restrict__ c2 = (const int2*)col;
    for (int e = blockIdx.x * blockDim.x + threadIdx.x; e < E2;
         e += gridDim.x * blockDim.x) {
        int2 c = c2[e];
        int2 r = r2[e];
        int p0 = atomicAdd(&g_cur[c.x], 1);
        g_bkt[p0] = r.x;
        int p1 = atomicAdd(&g_cur[c.y], 1);
        g_bkt[p1] = r.y;
    }
    if ((E & 1) && blockIdx.x == 0 && threadIdx.x == 0) {
        int p = atomicAdd(&g_cur[col[E - 1]], 1);
        g_bkt[p] = row[E - 1];
    }
}

__global__ void k_cvtW3(const float* __restrict__ W1, const float* __restrict__ W2,
                        const float* __restrict__ Wl) {
    int i = blockIdx.x * 256 + threadIdx.x;   // 192 blocks
    int which = i >> 14, j = i & 16383;
    const float* W = (which == 0) ? W1 : (which == 1) ? W2 : Wl;
    g_Wb[which][j] = __float2bfloat16(W[j]);
}

// ---------------- bf16 tensor-core GEMM: whole-K tiles, 1 sync (conv layers) --------
// P(bf16)[i][c] = dis[i] * sum_k X[i][k] * W[c][k]; 128x128x128 per block.
__global__ void __launch_bounds__(256)
k_gemm_bf16(const float* __restrict__ Xf, int useXf, int widx, int n) {
    extern __shared__ __nv_bfloat16 sm[];
    __nv_bfloat16* Xs = sm;                       // [128][GSTRIDE]
    __nv_bfloat16* Ws = sm + 128 * GSTRIDE;       // [128][GSTRIDE]

    const __nv_bfloat16* __restrict__ Hb = (const __nv_bfloat16*)g_H;
    const __nv_bfloat16* __restrict__ Wb = g_Wb[widx];

    int row0 = blockIdx.x * 128;
    int tid = threadIdx.x;
    int wid = tid >> 5, lane = tid & 31;
    int gid = lane >> 2, tig = lane & 3;
    int wm = wid >> 2, wn = wid & 3;
    int mbase = wm * 64, nbase = wn * 32;

    if (useXf) {
#pragma unroll
        for (int p = 0; p < 16; p++) {
            int f = tid + p * 256;
            int r = f >> 5, c4 = f & 31;
            float4 v = make_float4(0.f, 0.f, 0.f, 0.f);
            int gr = row0 + r;
            if (gr < n) v = *(const float4*)&Xf[(size_t)gr * CD + c4 * 4];
            *(uint2*)&Xs[r * GSTRIDE + c4 * 4] =
                make_uint2(pack_bf16x2(v.x, v.y), pack_bf16x2(v.z, v.w));
        }
    } else {
#pragma unroll
        for (int p = 0; p < 8; p++) {
            int f = tid + p * 256;
            int r = f >> 4, c8 = f & 15;
            uint4 v = make_uint4(0, 0, 0, 0);
            int gr = row0 + r;
            if (gr < n) v = *(const uint4*)&Hb[(size_t)gr * CD + c8 * 8];
            *(uint4*)&Xs[r * GSTRIDE + c8 * 8] = v;
        }
    }
#pragma unroll
    for (int p = 0; p < 8; p++) {
        int f = tid + p * 256;
        int r = f >> 4, c8 = f & 15;
        *(uint4*)&Ws[r * GSTRIDE + c8 * 8] = *(const uint4*)&Wb[(size_t)r * CD + c8 * 8];
    }
    __syncthreads();

    float acc[4][4][4];
#pragma unroll
    for (int a = 0; a < 4; a++)
#pragma unroll
        for (int b = 0; b < 4; b++)
#pragma unroll
            for (int c = 0; c < 4; c++) acc[a][b][c] = 0.0f;

#pragma unroll
    for (int kb = 0; kb < 128; kb += 16) {
        unsigned int af[4][4];
#pragma unroll
        for (int mt = 0; mt < 4; mt++) {
            int r = mbase + mt * 16 + gid;
            af[mt][0] = *(const unsigned int*)&Xs[r * GSTRIDE + kb + 2 * tig];
            af[mt][1] = *(const unsigned int*)&Xs[(r + 8) * GSTRIDE + kb + 2 * tig];
            af[mt][2] = *(const unsigned int*)&Xs[r * GSTRIDE + kb + 2 * tig + 8];
            af[mt][3] = *(const unsigned int*)&Xs[(r + 8) * GSTRIDE + kb + 2 * tig + 8];
        }
        unsigned int bfr[4][2];
#pragma unroll
        for (int nt = 0; nt < 4; nt++) {
            int cn = nbase + nt * 8 + gid;
            bfr[nt][0] = *(const unsigned int*)&Ws[cn * GSTRIDE + kb + 2 * tig];
            bfr[nt][1] = *(const unsigned int*)&Ws[cn * GSTRIDE + kb + 2 * tig + 8];
        }
#pragma unroll
        for (int mt = 0; mt < 4; mt++)
#pragma unroll
            for (int nt = 0; nt < 4; nt++) {
                asm("mma.sync.aligned.m16n8k16.row.col.f32.bf16.bf16.f32 "
                    "{%0,%1,%2,%3}, {%4,%5,%6,%7}, {%8,%9}, {%0,%1,%2,%3};"
                    : "+f"(acc[mt][nt][0]), "+f"(acc[mt][nt][1]),
                      "+f"(acc[mt][nt][2]), "+f"(acc[mt][nt][3])
                    : "r"(af[mt][0]), "r"(af[mt][1]), "r"(af[mt][2]), "r"(af[mt][3]),
                      "r"(bfr[nt][0]), "r"(bfr[nt][1]));
            }
    }

    __nv_bfloat16* Pb = (__nv_bfloat16*)g_P;
#pragma unroll
    for (int mt = 0; mt < 4; mt++) {
        int r0 = row0 + mbase + mt * 16 + gid;
        int r1 = r0 + 8;
        float s0 = (r0 < n) ? g_dis[r0] : 0.0f;
        float s1 = (r1 < n) ? g_dis[r1] : 0.0f;
#pragma unroll
        for (int nt = 0; nt < 4; nt++) {
            int cn = nbase + nt * 8 + tig * 2;
            if (r0 < n)
                *(unsigned int*)&Pb[(size_t)r0 * CD + cn] =
                    pack_bf16x2(acc[mt][nt][0] * s0, acc[mt][nt][1] * s0);
            if (r1 < n)
                *(unsigned int*)&Pb[(size_t)r1 * CD + cn] =
                    pack_bf16x2(acc[mt][nt][2] * s1, acc[mt][nt][3] * s1);
        }
    }
}

// ---------------- final layer: whole-K GEMM + bias + log_softmax fused --------------
__global__ void __launch_bounds__(256)
k_gemm_ls(const float* __restrict__ bl, float* __restrict__ out, int widx, int n) {
    extern __shared__ __nv_bfloat16 sm[];
    __nv_bfloat16* Xs = sm;
    __nv_bfloat16* Ws = sm + 128 * GSTRIDE;
    __shared__ float smx[128][4];
    __shared__ float sms[128][4];

    const __nv_bfloat16* __restrict__ Hb = (const __nv_bfloat16*)g_H;
    const __nv_bfloat16* __restrict__ Wb = g_Wb[widx];

    int row0 = blockIdx.x * 128;
    int tid = threadIdx.x;
    int wid = tid >> 5, lane = tid & 31;
    int gid = lane >> 2, tig = lane & 3;
    int wm = wid >> 2, wn = wid & 3;
    int mbase = wm * 64, nbase = wn * 32;

#pragma unroll
    for (int p = 0; p < 8; p++) {
        int f = tid + p * 256;
        int r = f >> 4, c8 = f & 15;
        uint4 v = make_uint4(0, 0, 0, 0);
        int gr = row0 + r;
        if (gr < n) v = *(const uint4*)&Hb[(size_t)gr * CD + c8 * 8];
        *(uint4*)&Xs[r * GSTRIDE + c8 * 8] = v;
    }
#pragma unroll
    for (int p = 0; p < 8; p++) {
        int f = tid + p * 256;
        int r = f >> 4, c8 = f & 15;
        *(uint4*)&Ws[r * GSTRIDE + c8 * 8] = *(const uint4*)&Wb[(size_t)r * CD + c8 * 8];
    }
    __syncthreads();

    float acc[4][4][4];
#pragma unroll
    for (int a = 0; a < 4; a++)
#pragma unroll
        for (int b = 0; b < 4; b++)
#pragma unroll
            for (int c = 0; c < 4; c++) acc[a][b][c] = 0.0f;

#pragma unroll
    for (int kb = 0; kb < 128; kb += 16) {
        unsigned int af[4][4];
#pragma unroll
        for (int mt = 0; mt < 4; mt++) {
            int r = mbase + mt * 16 + gid;
            af[mt][0] = *(const unsigned int*)&Xs[r * GSTRIDE + kb + 2 * tig];
            af[mt][1] = *(const unsigned int*)&Xs[(r + 8) * GSTRIDE + kb + 2 * tig];
            af[mt][2] = *(const unsigned int*)&Xs[r * GSTRIDE + kb + 2 * tig + 8];
            af[mt][3] = *(const unsigned int*)&Xs[(r + 8) * GSTRIDE + kb + 2 * tig + 8];
        }
        unsigned int bfr[4][2];
#pragma unroll
        for (int nt = 0; nt < 4; nt++) {
            int cn = nbase + nt * 8 + gid;
            bfr[nt][0] = *(const unsigned int*)&Ws[cn * GSTRIDE + kb + 2 * tig];
            bfr[nt][1] = *(const unsigned int*)&Ws[cn * GSTRIDE + kb + 2 * tig + 8];
        }
#pragma unroll
        for (int mt = 0; mt < 4; mt++)
#pragma unroll
            for (int nt = 0; nt < 4; nt++) {
                asm("mma.sync.aligned.m16n8k16.row.col.f32.bf16.bf16.f32 "
                    "{%0,%1,%2,%3}, {%4,%5,%6,%7}, {%8,%9}, {%0,%1,%2,%3};"
                    : "+f"(acc[mt][nt][0]), "+f"(acc[mt][nt][1]),
                      "+f"(acc[mt][nt][2]), "+f"(acc[mt][nt][3])
                    : "r"(af[mt][0]), "r"(af[mt][1]), "r"(af[mt][2]), "r"(af[mt][3]),
                      "r"(bfr[nt][0]), "r"(bfr[nt][1]));
            }
    }

    float bv[4][2];
#pragma unroll
    for (int nt = 0; nt < 4; nt++) {
        int cn = nbase + nt * 8 + tig * 2;
        float2 b = *(const float2*)&bl[cn];
        bv[nt][0] = b.x; bv[nt][1] = b.y;
    }
#pragma unroll
    for (int mt = 0; mt < 4; mt++)
#pragma unroll
        for (int nt = 0; nt < 4; nt++) {
            acc[mt][nt][0] += bv[nt][0];
            acc[mt][nt][1] += bv[nt][1];
            acc[mt][nt][2] += bv[nt][0];
            acc[mt][nt][3] += bv[nt][1];
        }

#pragma unroll
    for (int mt = 0; mt < 4; mt++) {
        float m0 = -1e30f, m1 = -1e30f;
#pragma unroll
        for (int nt = 0; nt < 4; nt++) {
            m0 = fmaxf(m0, fmaxf(acc[mt][nt][0], acc[mt][nt][1]));
            m1 = fmaxf(m1, fmaxf(acc[mt][nt][2], acc[mt][nt][3]));
        }
        m0 = fmaxf(m0, __shfl_xor_sync(0xFFFFFFFFu, m0, 1));
        m0 = fmaxf(m0, __shfl_xor_sync(0xFFFFFFFFu, m0, 2));
        m1 = fmaxf(m1, __shfl_xor_sync(0xFFFFFFFFu, m1, 1));
        m1 = fmaxf(m1, __shfl_xor_sync(0xFFFFFFFFu, m1, 2));
        if (tig == 0) {
            smx[mbase + mt * 16 + gid][wn] = m0;
            smx[mbase + mt * 16 + gid + 8][wn] = m1;
        }
    }
    __syncthreads();

#pragma unroll
    for (int mt = 0; mt < 4; mt++) {
        int lr0 = mbase + mt * 16 + gid;
        int lr1 = lr0 + 8;
        float M0 = fmaxf(fmaxf(smx[lr0][0], smx[lr0][1]), fmaxf(smx[lr0][2], smx[lr0][3]));
        float M1 = fmaxf(fmaxf(smx[lr1][0], smx[lr1][1]), fmaxf(smx[lr1][2], smx[lr1][3]));
        float s0 = 0.0f, s1 = 0.0f;
#pragma unroll
        for (int nt = 0; nt < 4; nt++) {
            s0 += expf(acc[mt][nt][0] - M0) + expf(acc[mt][nt][1] - M0);
            s1 += expf(acc[mt][nt][2] - M1) + expf(acc[mt][nt][3] - M1);
        }
        s0 += __shfl_xor_sync(0xFFFFFFFFu, s0, 1);
        s0 += __shfl_xor_sync(0xFFFFFFFFu, s0, 2);
        s1 += __shfl_xor_sync(0xFFFFFFFFu, s1, 1);
        s1 += __shfl_xor_sync(0xFFFFFFFFu, s1, 2);
        if (tig == 0) {
            sms[lr0][wn] = s0;
            sms[lr1][wn] = s1;
        }
    }
    __syncthreads();

#pragma unroll
    for (int mt = 0; mt < 4; mt++) {
        int lr0 = mbase + mt * 16 + gid;
        int lr1 = lr0 + 8;
        int r0 = row0 + lr0, r1 = row0 + lr1;
        float M0 = fmaxf(fmaxf(smx[lr0][0], smx[lr0][1]), fmaxf(smx[lr0][2], smx[lr0][3]));
        float M1 = fmaxf(fmaxf(smx[lr1][0], smx[lr1][1]), fmaxf(smx[lr1][2], smx[lr1][3]));
        float l0 = M0 + logf(sms[lr0][0] + sms[lr0][1] + sms[lr0][2] + sms[lr0][3]);
        float l1 = M1 + logf(sms[lr1][0] + sms[lr1][1] + sms[lr1][2] + sms[lr1][3]);
#pragma unroll
        for (int nt = 0; nt < 4; nt++) {
            int cn = nbase + nt * 8 + tig * 2;
            if (r0 < n)
                *(float2*)&out[(size_t)r0 * CD + cn] =
                    make_float2(acc[mt][nt][0] - l0, acc[mt][nt][1] - l0);
            if (r1 < n)
                *(float2*)&out[(size_t)r1 * CD + cn] =
                    make_float2(acc[mt][nt][2] - l1, acc[mt][nt][3] - l1);
        }
    }
}

// ---------------- gather (cnt derived from off; otherwise champion-exact) -----------
__global__ void k_gather(const float* __restrict__ bias, int n, int E) {
    int w = (blockIdx.x * blockDim.x + threadIdx.x) >> 5;
    if (w >= n) return;
    int lane = threadIdx.x & 31;

    const uint2* __restrict__ P2 = (const uint2*)g_P;
    uint2 sv = P2[(size_t)w * 32 + lane];
    float ax = __low2float(*(__nv_bfloat162*)&sv.x);
    float ay = __high2float(*(__nv_bfloat162*)&sv.x);
    float az = __low2float(*(__nv_bfloat162*)&sv.y);
    float aw = __high2float(*(__nv_bfloat162*)&sv.y);

    int o = g_off[w];
    int c = ((w + 1 < n) ? g_off[w + 1] : E) - o;
    int j = 0;
    for (; j + 2 <= c; j += 2) {
        int r0 = g_bkt[o + j];
        int r1 = g_bkt[o + j + 1];
        uint2 v0 = P2[(size_t)r0 * 32 + lane];
        uint2 v1 = P2[(size_t)r1 * 32 + lane];
        ax += __low2float(*(__nv_bfloat162*)&v0.x);
        ay += __high2float(*(__nv_bfloat162*)&v0.x);
        az += __low2float(*(__nv_bfloat162*)&v0.y);
        aw += __high2float(*(__nv_bfloat162*)&v0.y);
        ax += __low2float(*(__nv_bfloat162*)&v1.x);
        ay += __high2float(*(__nv_bfloat162*)&v1.x);
        az += __low2float(*(__nv_bfloat162*)&v1.y);
        aw += __high2float(*(__nv_bfloat162*)&v1.y);
    }
    if (j < c) {
        int r0 = g_bkt[o + j];
        uint2 v0 = P2[(size_t)r0 * 32 + lane];
        ax += __low2float(*(__nv_bfloat162*)&v0.x);
        ay += __high2float(*(__nv_bfloat162*)&v0.x);
        az += __low2float(*(__nv_bfloat162*)&v0.y);
        aw += __high2float(*(__nv_bfloat162*)&v0.y);
    }

    float s = g_dis[w];
    float4 b = *(const float4*)&bias[lane * 4];
    float ox = fmaxf(fmaf(ax, s, b.x), 0.0f);
    float oy = fmaxf(fmaf(ay, s, b.y), 0.0f);
    float oz = fmaxf(fmaf(az, s, b.z), 0.0f);
    float ow = fmaxf(fmaf(aw, s, b.w), 0.0f);
    ((uint2*)g_H)[(size_t)w * 32 + lane] =
        make_uint2(pack_bf16x2(ox, oy), pack_bf16x2(oz, ow));
}

// ---------------- launch ----------------
extern "C" void kernel_launch(void* const* d_in, const int* in_sizes, int n_in,
                              void* d_out, int out_size) {
    const float* x  = (const float*)d_in[0];
    const int*   ei = (const int*)d_in[1];
    const float* W1 = (const float*)d_in[2];
    const float* b1 = (const float*)d_in[3];
    const float* W2 = (const float*)d_in[4];
    const float* b2 = (const float*)d_in[5];
    const float* Wl = (const float*)d_in[6];
    const float* bl = (const float*)d_in[7];

    int n = in_sizes[0] / CD;
    int E = in_sizes[1] / 2;
    const int* row = ei;
    const int* col = ei + E;

    int nb256 = (n + 255) / 256;
    int nbScan = (n + 1023) / 1024;
    int gatherB = (n + 7) / 8;
    int gemmB = (n + 127) / 128;

    static cudaStream_t s1 = nullptr;
    static cudaEvent_t evFork = nullptr, evDis = nullptr, evJoin = nullptr,
                       evJoin2 = nullptr;
    if (s1 == nullptr) {
        cudaFuncSetAttribute(k_gemm_bf16,
                             cudaFuncAttributeMaxDynamicSharedMemorySize, GEMM_SMEM);
        cudaFuncSetAttribute(k_gemm_ls,
                             cudaFuncAttributeMaxDynamicSharedMemorySize, GEMM_SMEM);
        cudaStreamCreateWithFlags(&s1, cudaStreamNonBlocking);
        cudaEventCreateWithFlags(&evFork, cudaEventDisableTiming);
        cudaEventCreateWithFlags(&evDis, cudaEventDisableTiming);
        cudaEventCreateWithFlags(&evJoin, cudaEventDisableTiming);
        cudaEventCreateWithFlags(&evJoin2, cudaEventDisableTiming);
    }

    // fork FIRST so preproc overlaps cvtW (g_cnt is zero at entry by invariant)
    cudaEventRecord(evFork, 0);
    cudaStreamWaitEvent(s1, evFork, 0);

    k_count<<<2048, 256, 0, s1>>>(col, E);
    k_scan1<<<nbScan, 1024, 0, s1>>>(n);      // writes dis + per-block off/partials
    cudaEventRecord(evDis, s1);               // dis ready

    k_scan23<<<nb256, 256, 0, s1>>>(nbScan, n);
    k_fill<<<2048, 256, 0, s1>>>(row, col, E);
    cudaEventRecord(evJoin, s1);

    k_zero_cnt<<<nb256, 256, 0, s1>>>(n);     // restore invariant; hidden behind gather1
    cudaEventRecord(evJoin2, s1);

    // stream 0: weights, then conv1 GEMM once dis is ready
    k_cvtW3<<<192, 256>>>(W1, W2, Wl);
    cudaStreamWaitEvent(0, evDis, 0);
    k_gemm_bf16<<<gemmB, 256, GEMM_SMEM>>>(x, 1, 0, n);

    cudaStreamWaitEvent(0, evJoin, 0);
    k_gather<<<gatherB, 256>>>(b1, n, E);

    // conv2
    k_gemm_bf16<<<gemmB, 256, GEMM_SMEM>>>(nullptr, 0, 1, n);
    k_gather<<<gatherB, 256>>>(b2, n, E);

    // join the tail zero, then fused linear + log_softmax
    cudaStreamWaitEvent(0, evJoin2, 0);
    k_gemm_ls<<<gemmB, 256, GEMM_SMEM>>>(bl, (float*)d_out, 2, n);
}